// round 9
// baseline (speedup 1.0000x reference)
#include <cuda_runtime.h>
#include <math.h>

#define NN  4096
#define KK  32
#define DD  64
#define BSZ 8
#define TT  32
#define HSZ 256
#define TILE 64

typedef unsigned long long u64;

// ---------------- persistent device scratch (float4-aligned) ----------------
__device__ float4 g_wsig4[BSZ*NN*KK/4];
__device__ float  g_d[BSZ*NN];
__device__ float  g_dec[BSZ*NN];
__device__ float  g_prim[BSZ*NN*DD];
__device__ float4 g_sconst4[(size_t)BSZ*NN*HSZ/4];
__device__ float4 g_mconst4[(size_t)BSZ*NN*HSZ/4];
__device__ float4 g_h4[BSZ*NN*DD/4];
__device__ float4 g_msg4[2][BSZ*NN*DD/4];
__device__ float4 g_Wsi4[DD*HSZ/4];    // state_w1[:, :64]  -> [j][h]
__device__ float4 g_Ws24[HSZ*DD/4];    // state_w2          -> [h][o]
__device__ float4 g_Wmh4[DD*HSZ/4];    // msg_w1[:, :64]    -> [j][h]
__device__ float4 g_Wm24[HSZ*DD/4];    // msg_w2            -> [h][o]
__device__ float  g_WsC[129*HSZ];      // const-GEMM weights [j][h]
__device__ float  g_WmC[129*HSZ];

// ---------------- fast math + f32x2 helpers ----------------
__device__ __forceinline__ float ftanh(float x) {
    float ax = fabsf(x);
    float e  = __expf(-2.f*ax);
    float t  = __fdividef(1.f - e, 1.f + e);
    return copysignf(t, x);
}
__device__ __forceinline__ float fsigmoid(float x) {
    return __fdividef(1.f, 1.f + __expf(-x));
}
__device__ __forceinline__ u64 pack2(float x) {
    u64 r; unsigned xi = __float_as_uint(x);
    asm("mov.b64 %0, {%1,%1};" : "=l"(r) : "r"(xi));
    return r;
}
__device__ __forceinline__ float2 unpack2(u64 v) {
    unsigned lo, hi;
    asm("mov.b64 {%0,%1}, %2;" : "=r"(lo), "=r"(hi) : "l"(v));
    return make_float2(__uint_as_float(lo), __uint_as_float(hi));
}
__device__ __forceinline__ void ffma2(u64& d, u64 a, u64 b) {
    asm("fma.rn.f32x2 %0, %1, %2, %0;" : "+l"(d) : "l"(a), "l"(b));
}

// ---------------- init: copy state, pack weights ----------------
__global__ void k_init(const float* __restrict__ h_in, const float* __restrict__ msg_in,
                       const float* __restrict__ sw1, const float* __restrict__ sw2,
                       const float* __restrict__ mw1, const float* __restrict__ mw2)
{
    int i0 = blockIdx.x*blockDim.x + threadIdx.x;
    int stride = gridDim.x*blockDim.x;
    float* gh   = (float*)g_h4;
    float* gm0  = (float*)g_msg4[0];
    float* Wsi  = (float*)g_Wsi4;  float* Ws2 = (float*)g_Ws24;
    float* Wmh  = (float*)g_Wmh4;  float* Wm2 = (float*)g_Wm24;
    for (int i = i0; i < BSZ*NN*DD; i += stride) { gh[i] = h_in[i]; gm0[i] = msg_in[i]; }
    for (int i = i0; i < DD*HSZ; i += stride) {
        int j = i >> 8, h = i & 255;
        Wsi[i] = sw1[h*193 + j];
        Wmh[i] = mw1[h*192 + j];
    }
    for (int i = i0; i < HSZ*DD; i += stride) {
        int h = i >> 6, o = i & 63;
        Ws2[i] = sw2[o*256 + h];
        Wm2[i] = mw2[o*256 + h];
    }
    for (int i = i0; i < 129*HSZ; i += stride) {
        int j = i >> 8, h = i & 255;
        g_WsC[i] = (j < 128) ? sw1[h*193 + 64 + j] : sw1[h*193 + 192];
        g_WmC[i] = (j < 128) ? mw1[h*192 + 64 + j] : 0.f;
    }
}

// ---------------- per-neuron modulation MLP ----------------
__global__ void k_mod(const float* __restrict__ h_in, const float* __restrict__ heb,
                      const float* __restrict__ dec_in, const float* __restrict__ prim_in,
                      const float* __restrict__ wconn_in,
                      const float* __restrict__ mw1, const float* __restrict__ mb1,
                      const float* __restrict__ mw2, const float* __restrict__ mb2,
                      const float* __restrict__ nid)
{
    const int n = blockIdx.x;
    const int tid = threadIdx.x;
    const int warp = tid >> 5, lane = tid & 31;
    __shared__ float xs[BSZ*225];
    __shared__ float hid[BSZ*64];
    __shared__ float dlt[BSZ*97];

    for (int i = tid; i < BSZ*225; i += 256) {
        int b = i / 225, j = i - b*225;
        size_t bn = (size_t)b*NN + n;
        float v;
        if (j < 32)        v = heb[bn*32 + j];
        else if (j < 96)   v = h_in[bn*64 + (j-32)];
        else if (j == 96)  v = dec_in[bn];
        else if (j < 161)  v = prim_in[bn*64 + (j-97)];
        else               v = nid[(size_t)n*64 + (j-161)];
        xs[i] = v;
    }
    __syncthreads();

    const float* w1 = mw1 + (size_t)n*64*225;
    for (int hh = warp; hh < 64; hh += 8) {
        float acc[BSZ];
        #pragma unroll
        for (int b = 0; b < BSZ; b++) acc[b] = 0.f;
        for (int j = lane; j < 225; j += 32) {
            float w = w1[hh*225 + j];
            #pragma unroll
            for (int b = 0; b < BSZ; b++) acc[b] += w * xs[b*225 + j];
        }
        #pragma unroll
        for (int off = 16; off; off >>= 1) {
            #pragma unroll
            for (int b = 0; b < BSZ; b++) acc[b] += __shfl_xor_sync(0xffffffffu, acc[b], off);
        }
        if (lane == 0) {
            float bb = mb1[(size_t)n*64 + hh];
            #pragma unroll
            for (int b = 0; b < BSZ; b++) hid[b*64 + hh] = ftanh(acc[b] + bb);
        }
    }
    __syncthreads();

    const float* w2 = mw2 + (size_t)n*64*97;
    for (int o = warp; o < 97; o += 8) {
        float acc[BSZ];
        #pragma unroll
        for (int b = 0; b < BSZ; b++) acc[b] = 0.f;
        #pragma unroll
        for (int j2 = 0; j2 < 2; ++j2) {
            int j = lane + 32*j2;
            float w = w2[(size_t)j*97 + o];
            #pragma unroll
            for (int b = 0; b < BSZ; b++) acc[b] += w * hid[b*64 + j];
        }
        #pragma unroll
        for (int off = 16; off; off >>= 1) {
            #pragma unroll
            for (int b = 0; b < BSZ; b++) acc[b] += __shfl_xor_sync(0xffffffffu, acc[b], off);
        }
        if (lane == 0) {
            float bb = mb2[(size_t)n*97 + o];
            #pragma unroll
            for (int b = 0; b < BSZ; b++) dlt[b*97 + o] = acc[b] + bb;
        }
    }
    __syncthreads();

    float* wsig = (float*)g_wsig4;
    for (int i = tid; i < BSZ*KK; i += 256) {
        int b = i >> 5, k = i & 31;
        size_t bn = (size_t)b*NN + n;
        wsig[bn*32 + k] = fsigmoid(wconn_in[bn*32 + k] + dlt[b*97 + k]);
    }
    if (tid < BSZ) {
        size_t bn = (size_t)tid*NN + n;
        float v = dec_in[bn] + dlt[tid*97 + 32];
        g_dec[bn] = v;
        g_d[bn] = fsigmoid(v);
    }
    if (warp < BSZ) {
        int b = warp;
        size_t bn = (size_t)b*NN + n;
        float p0 = prim_in[bn*64 + lane]      + dlt[b*97 + 33 + lane];
        float p1 = prim_in[bn*64 + lane + 32] + dlt[b*97 + 33 + lane + 32];
        float ss = p0*p0 + p1*p1;
        #pragma unroll
        for (int off = 16; off; off >>= 1) ss += __shfl_xor_sync(0xffffffffu, ss, off);
        float sc = rsqrtf(ss*(1.f/64.f) + 1e-6f);
        g_prim[bn*64 + lane]      = p0*sc;
        g_prim[bn*64 + lane + 32] = p1*sc;
    }
}

// ---------------- state_const / msg_const (register-tiled GEMM) ----------------
__global__ __launch_bounds__(256, 4)
void k_const(const float* __restrict__ sb1, const float* __restrict__ mb1_,
             const float* __restrict__ nid)
{
    __shared__ float xs[64*132];
    const int tid = threadIdx.x;
    const int r0 = blockIdx.x * 64;
    const int which = blockIdx.y;              // 1 = state, 0 = msg
    const float* WC = which ? g_WsC : g_WmC;
    const float* b1 = which ? sb1 : mb1_;
    float* outp     = which ? (float*)g_sconst4 : (float*)g_mconst4;

    for (int i = tid; i < 64*132; i += 256) {
        int rr = i / 132, j = i - rr*132;
        size_t r = (size_t)(r0 + rr);
        int nn_ = (int)(r & (NN-1));
        float v = 0.f;
        if (j < 64)        v = g_prim[r*64 + j];
        else if (j < 128)  v = nid[(size_t)nn_*64 + (j-64)];
        else if (j == 128) v = g_dec[r];
        xs[i] = v;
    }
    __syncthreads();

    const int ty = tid >> 5, tx = tid & 31;
    float acc[8][8];
    #pragma unroll
    for (int i = 0; i < 8; i++)
        #pragma unroll
        for (int u = 0; u < 8; u++) acc[i][u] = 0.f;
    for (int j = 0; j < 129; ++j) {
        float a[8], w[8];
        #pragma unroll
        for (int i = 0; i < 8; i++) a[i] = xs[(ty*8+i)*132 + j];
        #pragma unroll
        for (int u = 0; u < 8; u++) w[u] = __ldg(WC + j*256 + tx + 32*u);
        #pragma unroll
        for (int i = 0; i < 8; i++)
            #pragma unroll
            for (int u = 0; u < 8; u++) acc[i][u] += a[i]*w[u];
    }
    #pragma unroll
    for (int i = 0; i < 8; i++) {
        int r = r0 + ty*8 + i;
        #pragma unroll
        for (int u = 0; u < 8; u++) {
            int c = tx + 32*u;
            outp[(size_t)r*256 + c] = acc[i][u] + __ldg(b1 + c);
        }
    }
}

// ---------------- per-warp wide GEMM: C[8x256] = A[8x64] @ W + const, tanh ----------------
// s_x, s_hid are THIS WARP's private slices. Warp = 8 rows x 256 cols, lane ln -> cols 4ln..4ln+3, 4ln+128..
__device__ __forceinline__ void gemm_wide_warp(const float* s_x, float* s_hid,
                                               const float4* __restrict__ W4,
                                               const float4* __restrict__ cst, // global-row base *64
                                               int ln)
{
    u64 acc[8][4];
    #pragma unroll
    for (int i = 0; i < 8; i++)
        #pragma unroll
        for (int u = 0; u < 4; u++) acc[i][u] = 0ull;

    #pragma unroll 2
    for (int j = 0; j < 64; j += 2) {
        float2 a2[8];
        #pragma unroll
        for (int i = 0; i < 8; i++)
            a2[i] = *(const float2*)&s_x[i*68 + j];
        #pragma unroll
        for (int jj = 0; jj < 2; jj++) {
            const ulonglong2* wr = (const ulonglong2*)(W4 + (size_t)(j+jj)*64);
            ulonglong2 w0 = __ldg(wr + ln);
            ulonglong2 w1 = __ldg(wr + ln + 32);
            #pragma unroll
            for (int i = 0; i < 8; i++) {
                u64 ap = pack2(jj ? a2[i].y : a2[i].x);
                ffma2(acc[i][0], ap, w0.x);
                ffma2(acc[i][1], ap, w0.y);
                ffma2(acc[i][2], ap, w1.x);
                ffma2(acc[i][3], ap, w1.y);
            }
        }
    }
    #pragma unroll
    for (int i = 0; i < 8; i++) {
        float4 c0 = __ldg(cst + (size_t)i*64 + ln);
        float4 c1 = __ldg(cst + (size_t)i*64 + 32 + ln);
        float2 p0 = unpack2(acc[i][0]), p1 = unpack2(acc[i][1]);
        float2 p2 = unpack2(acc[i][2]), p3 = unpack2(acc[i][3]);
        float4 o0 = make_float4(ftanh(p0.x+c0.x), ftanh(p0.y+c0.y),
                                ftanh(p1.x+c0.z), ftanh(p1.y+c0.w));
        float4 o1 = make_float4(ftanh(p2.x+c1.x), ftanh(p2.y+c1.y),
                                ftanh(p3.x+c1.z), ftanh(p3.y+c1.w));
        *(float4*)&s_hid[i*260 + ln*4]       = o0;
        *(float4*)&s_hid[i*260 + 128 + ln*4] = o1;
    }
}

// ---------------- per-warp narrow GEMM: acc[4 rows][2 pairs] += H[8x256] @ W ----------------
// half-warp tz = ln>>4 -> local rows tz*4..+4; tq = ln&15 -> cols 4tq..4tq+3
__device__ __forceinline__ void gemm_narrow_warp(const float* s_hid,
                                                 const float4* __restrict__ W4,
                                                 int ln, u64 acc[4][2])
{
    const int tz = ln >> 4, tq = ln & 15;
    #pragma unroll
    for (int i = 0; i < 4; i++) { acc[i][0] = 0ull; acc[i][1] = 0ull; }
    #pragma unroll 2
    for (int k = 0; k < 256; k += 4) {
        float4 a4[4];
        #pragma unroll
        for (int i = 0; i < 4; i++)
            a4[i] = *(const float4*)&s_hid[(tz*4+i)*260 + k];
        #pragma unroll
        for (int kk = 0; kk < 4; kk++) {
            ulonglong2 w = __ldg((const ulonglong2*)(W4 + (size_t)(k+kk)*16) + tq);
            #pragma unroll
            for (int i = 0; i < 4; i++) {
                float a = (kk == 0) ? a4[i].x : (kk == 1) ? a4[i].y
                        : (kk == 2) ? a4[i].z : a4[i].w;
                u64 ap = pack2(a);
                ffma2(acc[i][0], ap, w.x);
                ffma2(acc[i][1], ap, w.y);
            }
        }
    }
}

// ---------------- fused recurrent step (fully warp-synchronous) ----------------
// Warp w owns tile rows 8w..8w+8 through all phases. No __syncthreads at all.
// smem: per-warp s_hid (8x260) x 8 warps | per-warp s_x (8x68) x 8 warps
#define SHID_WARP (8*260)
#define SX_WARP   (8*68)
#define STEP_SMEM ((8*SHID_WARP + 8*SX_WARP)*4)

__global__ __launch_bounds__(256, 2)
void k_step(int t, const float* __restrict__ cc, const int* __restrict__ conn,
            const float* __restrict__ nid, const float* __restrict__ sb2,
            const float* __restrict__ mb2, float* __restrict__ out)
{
    extern __shared__ float sm[];
    const int tid = threadIdx.x;
    const int w   = tid >> 5, ln = tid & 31;
    float* s_hid = sm + w*SHID_WARP;
    float* s_x   = sm + 8*SHID_WARP + w*SX_WARP;

    const int b  = blockIdx.y;
    const int nt = blockIdx.x;
    const int n0 = nt*TILE;
    const int r0 = w*8;                       // warp's row base within tile
    const int sel = t & 1;
    const size_t growbase = (size_t)b*NN + n0 + r0;   // global row base for this warp

    // ---- phase 0: gather (+inject) -> this warp's 8 rows of s_x ----
    {
        const u64*    mq  = (const u64*)((const float*)g_msg4[sel] + (size_t)b*NN*64);
        const int4*   cn4 = (const int4*)conn;
        const float4* ws4 = (const float4*)g_wsig4;
        #pragma unroll 1
        for (int g = 0; g < 8; ++g) {
            const int n = n0 + r0 + g;
            const size_t cb = (size_t)n*8;
            const size_t wb = ((size_t)b*NN + n)*8;
            u64 a0 = 0ull, a1 = 0ull;
            #pragma unroll
            for (int kq = 0; kq < 8; ++kq) {
                int4   id = __ldg(cn4 + cb + kq);
                float4 wt = __ldg(ws4 + wb + kq);
                ffma2(a0, pack2(wt.x), mq[(size_t)id.x*32 + ln]);
                ffma2(a1, pack2(wt.y), mq[(size_t)id.y*32 + ln]);
                ffma2(a0, pack2(wt.z), mq[(size_t)id.z*32 + ln]);
                ffma2(a1, pack2(wt.w), mq[(size_t)id.w*32 + ln]);
            }
            float2 v0 = unpack2(a0), v1 = unpack2(a1);
            float x0 = v0.x + v1.x, x1 = v0.y + v1.y;
            if ((n & 127) < 4) {
                float2 cv = *(const float2*)(cc + ((size_t)b*TT + t)*2048 + (n>>7)*64 + ln*2);
                x0 += cv.x; x1 += cv.y;
            }
            *(float2*)&s_x[g*68 + ln*2] = make_float2(x0, x1);
        }
    }
    __syncwarp();

    // ---- phase 1: hid = tanh(recv @ Wsi + state_const) ----
    gemm_wide_warp(s_x, s_hid, g_Wsi4, g_sconst4 + growbase*64, ln);
    __syncwarp();

    // ---- phase 2: upd = tanh(hid @ Ws2 + sb2); h = d*h + (1-d)*upd ----
    {
        u64 acc[4][2];
        gemm_narrow_warp(s_hid, g_Ws24, ln, acc);
        const int tz = ln >> 4, tq = ln & 15;
        float4 bb = __ldg((const float4*)sb2 + tq);
        #pragma unroll
        for (int i = 0; i < 4; i++) {
            int rl = tz*4 + i;
            size_t row = growbase + rl;
            float dv = g_d[row];
            float2 p0 = unpack2(acc[i][0]), p1 = unpack2(acc[i][1]);
            float4 hb = g_h4[row*16 + tq];
            float u0 = ftanh(p0.x + bb.x), u1 = ftanh(p0.y + bb.y);
            float u2 = ftanh(p1.x + bb.z), u3 = ftanh(p1.y + bb.w);
            float4 hv = make_float4(dv*hb.x + (1.f-dv)*u0, dv*hb.y + (1.f-dv)*u1,
                                    dv*hb.z + (1.f-dv)*u2, dv*hb.w + (1.f-dv)*u3);
            g_h4[row*16 + tq] = hv;
            *(float4*)&s_x[rl*68 + tq*4] = hv;
        }
    }
    __syncwarp();

    // ---- phase 3: mh = tanh(h @ Wmh + msg_const) ----
    gemm_wide_warp(s_x, s_hid, g_Wmh4, g_mconst4 + growbase*64, ln);
    __syncwarp();

    // ---- phase 4: msg = tanh(mh @ Wm2 + mb2) + nid; in-register readout ----
    {
        u64 acc[4][2];
        gemm_narrow_warp(s_hid, g_Wm24, ln, acc);
        const int tz = ln >> 4, tq = ln & 15;
        float4 bb = __ldg((const float4*)mb2 + tq);
        float4* msgout = g_msg4[sel^1];
        float4 ro = make_float4(0.f, 0.f, 0.f, 0.f);
        #pragma unroll
        for (int i = 0; i < 4; i++) {
            int rl = tz*4 + i;
            int n = n0 + r0 + rl;
            size_t row = growbase + rl;
            float2 p0 = unpack2(acc[i][0]), p1 = unpack2(acc[i][1]);
            float4 nv = __ldg((const float4*)nid + (size_t)n*16 + tq);
            float4 mv = make_float4(ftanh(p0.x + bb.x) + nv.x, ftanh(p0.y + bb.y) + nv.y,
                                    ftanh(p1.x + bb.z) + nv.z, ftanh(p1.y + bb.w) + nv.w);
            msgout[row*16 + tq] = mv;
            ro.x += mv.x; ro.y += mv.y; ro.z += mv.z; ro.w += mv.w;
        }
        // rows 60..63 live in warp 7, half-warp tz=1 -> readout entirely in registers
        if ((nt & 1) && w == 7 && tz == 1) {
            float4 v = make_float4(0.25f*ro.x, 0.25f*ro.y, 0.25f*ro.z, 0.25f*ro.w);
            *(float4*)&out[((size_t)b*TT + t)*2048 + (nt >> 1)*64 + tq*4] = v;
        }
    }
}

// ---------------- launcher ----------------
extern "C" void kernel_launch(void* const* d_in, const int* in_sizes, int n_in,
                              void* d_out, int out_size)
{
    const float* cc      = (const float*)d_in[0];
    const float* h_in    = (const float*)d_in[1];
    const float* msg_in  = (const float*)d_in[2];
    const float* wconn   = (const float*)d_in[3];
    const float* declog  = (const float*)d_in[4];
    const float* prim_in = (const float*)d_in[5];
    const float* heb     = (const float*)d_in[6];
    const float* sw1     = (const float*)d_in[7];
    const float* sb1     = (const float*)d_in[8];
    const float* sw2     = (const float*)d_in[9];
    const float* sb2     = (const float*)d_in[10];
    const float* mw1     = (const float*)d_in[11];
    const float* mb1     = (const float*)d_in[12];
    const float* mw2     = (const float*)d_in[13];
    const float* mb2     = (const float*)d_in[14];
    const float* modw1   = (const float*)d_in[15];
    const float* modb1   = (const float*)d_in[16];
    const float* modw2   = (const float*)d_in[17];
    const float* modb2   = (const float*)d_in[18];
    const float* nid     = (const float*)d_in[19];
    const int*   conn    = (const int*)d_in[20];
    float* out = (float*)d_out;

    cudaFuncSetAttribute(k_step, cudaFuncAttributeMaxDynamicSharedMemorySize, STEP_SMEM);

    k_init<<<256, 256>>>(h_in, msg_in, sw1, sw2, mw1, mw2);
    k_mod<<<NN, 256>>>(h_in, heb, declog, prim_in, wconn,
                       modw1, modb1, modw2, modb2, nid);
    k_const<<<dim3(512, 2), 256>>>(sb1, mb1, nid);

    for (int t = 0; t < TT; ++t) {
        k_step<<<dim3(NN/TILE, 8), 256, STEP_SMEM>>>(t, cc, conn, nid, sb2, mb2, out);
    }
}

// round 10
// speedup vs baseline: 1.3287x; 1.3287x over previous
#include <cuda_runtime.h>
#include <math.h>
#include <stdint.h>

#define NN   4096
#define KK   32
#define DD   64
#define BSZ  8
#define TT   32
#define HSZ  256
#define ROWS (BSZ*NN)

typedef unsigned long long u64;

// ================= persistent device scratch =================
__device__ float4 g_wsig4[ROWS*KK/4];
__device__ float  g_d[ROWS];
__device__ float  g_dec[ROWS];
__device__ float  g_prim[ROWS*DD];
__device__ float  g_sconst[(size_t)ROWS*HSZ];   // [row][256]
__device__ float  g_mconst[(size_t)ROWS*HSZ];
__device__ float2 g_h2[ROWS*DD/2];              // [row][32 float2]
__device__ float2 g_msg2[2][ROWS*DD/2];
__device__ float  g_WsC[129*HSZ];               // const-GEMM weights [j][h]
__device__ float  g_WmC[129*HSZ];
// fragment-packed bf16 weights: phase p*4096 .. : uint4 = {b0h,b1h,b0l,b1l}
// p0 = Wsi (wide 64x256), p1 = Ws2 (narrow 256x64), p2 = Wmh, p3 = Wm2
__device__ uint4  g_Wpk[4*4096];

// ================= helpers =================
__device__ __forceinline__ float ftanh(float x) {
    float ax = fabsf(x);
    float e  = __expf(-2.f*ax);
    float t  = __fdividef(1.f - e, 1.f + e);
    return copysignf(t, x);
}
__device__ __forceinline__ float fsigmoid(float x) {
    return __fdividef(1.f, 1.f + __expf(-x));
}
__device__ __forceinline__ u64 pack2(float x) {
    u64 r; unsigned xi = __float_as_uint(x);
    asm("mov.b64 %0, {%1,%1};" : "=l"(r) : "r"(xi));
    return r;
}
__device__ __forceinline__ float2 unpack2(u64 v) {
    unsigned lo, hi;
    asm("mov.b64 {%0,%1}, %2;" : "=r"(lo), "=r"(hi) : "l"(v));
    return make_float2(__uint_as_float(lo), __uint_as_float(hi));
}
__device__ __forceinline__ void ffma2(u64& d, u64 a, u64 b) {
    asm("fma.rn.f32x2 %0, %1, %2, %0;" : "+l"(d) : "l"(a), "l"(b));
}
// split (a,b) into bf16 hi-pair and lo-pair; lower 16 bits = a
__device__ __forceinline__ void split2(float a, float b, uint32_t& hi, uint32_t& lo) {
    uint32_t h;
    asm("cvt.rn.bf16x2.f32 %0, %1, %2;" : "=r"(h) : "f"(b), "f"(a));
    float ra = a - __uint_as_float(h << 16);
    float rb = b - __uint_as_float(h & 0xffff0000u);
    uint32_t l;
    asm("cvt.rn.bf16x2.f32 %0, %1, %2;" : "=r"(l) : "f"(rb), "f"(ra));
    hi = h; lo = l;
}
__device__ __forceinline__ void ldm_x4(uint32_t* r, uint32_t addr) {
    asm volatile("ldmatrix.sync.aligned.m8n8.x4.shared.b16 {%0,%1,%2,%3}, [%4];"
        : "=r"(r[0]), "=r"(r[1]), "=r"(r[2]), "=r"(r[3]) : "r"(addr));
}
__device__ __forceinline__ void mma_bf16(float* d, const uint32_t* a,
                                         uint32_t b0, uint32_t b1) {
    asm volatile("mma.sync.aligned.m16n8k16.row.col.f32.bf16.bf16.f32 "
        "{%0,%1,%2,%3}, {%4,%5,%6,%7}, {%8,%9}, {%0,%1,%2,%3};"
        : "+f"(d[0]), "+f"(d[1]), "+f"(d[2]), "+f"(d[3])
        : "r"(a[0]), "r"(a[1]), "r"(a[2]), "r"(a[3]), "r"(b0), "r"(b1));
}
__device__ __forceinline__ uint32_t smem_u32(const void* p) {
    uint32_t a;
    asm("{ .reg .u64 t; cvta.to.shared.u64 t, %1; cvt.u32.u64 %0, t; }"
        : "=r"(a) : "l"(p));
    return a;
}

// ================= init: copy state, build const-W, pack mma weights =================
__global__ void k_init(const float* __restrict__ h_in, const float* __restrict__ msg_in,
                       const float* __restrict__ sw1, const float* __restrict__ sw2,
                       const float* __restrict__ mw1, const float* __restrict__ mw2)
{
    int i0 = blockIdx.x*blockDim.x + threadIdx.x;
    int stride = gridDim.x*blockDim.x;
    float* gh  = (float*)g_h2;
    float* gm0 = (float*)g_msg2[0];
    for (int i = i0; i < ROWS*DD; i += stride) { gh[i] = h_in[i]; gm0[i] = msg_in[i]; }
    for (int i = i0; i < 129*HSZ; i += stride) {
        int j = i >> 8, h = i & 255;
        g_WsC[i] = (j < 128) ? sw1[h*193 + 64 + j] : sw1[h*193 + 192];
        g_WmC[i] = (j < 128) ? mw1[h*192 + 64 + j] : 0.f;
    }
    // pack mma B fragments: W(k,n); lane: k0 = kt*16+(lane&3)*2, n = nt*8+lane>>2
    for (int e = i0; e < 4*4096; e += stride) {
        int p = e >> 12, r = e & 4095;
        int lane = r & 31, q = r >> 5;
        int NT = (p == 0 || p == 2) ? 32 : 8;
        int kt = q / NT, nt = q - kt*NT;
        int k0 = kt*16 + (lane & 3)*2;
        int n  = nt*8 + (lane >> 2);
        float w00, w01, w10, w11;
        if (p == 0)      { const float* s = sw1 + (size_t)n*193;
                           w00 = s[k0]; w01 = s[k0+1]; w10 = s[k0+8]; w11 = s[k0+9]; }
        else if (p == 1) { const float* s = sw2 + (size_t)n*256;
                           w00 = s[k0]; w01 = s[k0+1]; w10 = s[k0+8]; w11 = s[k0+9]; }
        else if (p == 2) { const float* s = mw1 + (size_t)n*192;
                           w00 = s[k0]; w01 = s[k0+1]; w10 = s[k0+8]; w11 = s[k0+9]; }
        else             { const float* s = mw2 + (size_t)n*256;
                           w00 = s[k0]; w01 = s[k0+1]; w10 = s[k0+8]; w11 = s[k0+9]; }
        uint32_t b0h, b0l, b1h, b1l;
        split2(w00, w01, b0h, b0l);
        split2(w10, w11, b1h, b1l);
        g_Wpk[e] = make_uint4(b0h, b1h, b0l, b1l);
    }
}

// ================= per-neuron modulation MLP (unchanged) =================
__global__ void k_mod(const float* __restrict__ h_in, const float* __restrict__ heb,
                      const float* __restrict__ dec_in, const float* __restrict__ prim_in,
                      const float* __restrict__ wconn_in,
                      const float* __restrict__ mw1, const float* __restrict__ mb1,
                      const float* __restrict__ mw2, const float* __restrict__ mb2,
                      const float* __restrict__ nid)
{
    const int n = blockIdx.x;
    const int tid = threadIdx.x;
    const int warp = tid >> 5, lane = tid & 31;
    __shared__ float xs[BSZ*225];
    __shared__ float hid[BSZ*64];
    __shared__ float dlt[BSZ*97];

    for (int i = tid; i < BSZ*225; i += 256) {
        int b = i / 225, j = i - b*225;
        size_t bn = (size_t)b*NN + n;
        float v;
        if (j < 32)        v = heb[bn*32 + j];
        else if (j < 96)   v = h_in[bn*64 + (j-32)];
        else if (j == 96)  v = dec_in[bn];
        else if (j < 161)  v = prim_in[bn*64 + (j-97)];
        else               v = nid[(size_t)n*64 + (j-161)];
        xs[i] = v;
    }
    __syncthreads();

    const float* w1 = mw1 + (size_t)n*64*225;
    for (int hh = warp; hh < 64; hh += 8) {
        float acc[BSZ];
        #pragma unroll
        for (int b = 0; b < BSZ; b++) acc[b] = 0.f;
        for (int j = lane; j < 225; j += 32) {
            float w = w1[hh*225 + j];
            #pragma unroll
            for (int b = 0; b < BSZ; b++) acc[b] += w * xs[b*225 + j];
        }
        #pragma unroll
        for (int off = 16; off; off >>= 1) {
            #pragma unroll
            for (int b = 0; b < BSZ; b++) acc[b] += __shfl_xor_sync(0xffffffffu, acc[b], off);
        }
        if (lane == 0) {
            float bb = mb1[(size_t)n*64 + hh];
            #pragma unroll
            for (int b = 0; b < BSZ; b++) hid[b*64 + hh] = ftanh(acc[b] + bb);
        }
    }
    __syncthreads();

    const float* w2 = mw2 + (size_t)n*64*97;
    for (int o = warp; o < 97; o += 8) {
        float acc[BSZ];
        #pragma unroll
        for (int b = 0; b < BSZ; b++) acc[b] = 0.f;
        #pragma unroll
        for (int j2 = 0; j2 < 2; ++j2) {
            int j = lane + 32*j2;
            float w = w2[(size_t)j*97 + o];
            #pragma unroll
            for (int b = 0; b < BSZ; b++) acc[b] += w * hid[b*64 + j];
        }
        #pragma unroll
        for (int off = 16; off; off >>= 1) {
            #pragma unroll
            for (int b = 0; b < BSZ; b++) acc[b] += __shfl_xor_sync(0xffffffffu, acc[b], off);
        }
        if (lane == 0) {
            float bb = mb2[(size_t)n*97 + o];
            #pragma unroll
            for (int b = 0; b < BSZ; b++) dlt[b*97 + o] = acc[b] + bb;
        }
    }
    __syncthreads();

    float* wsig = (float*)g_wsig4;
    for (int i = tid; i < BSZ*KK; i += 256) {
        int b = i >> 5, k = i & 31;
        size_t bn = (size_t)b*NN + n;
        wsig[bn*32 + k] = fsigmoid(wconn_in[bn*32 + k] + dlt[b*97 + k]);
    }
    if (tid < BSZ) {
        size_t bn = (size_t)tid*NN + n;
        float v = dec_in[bn] + dlt[tid*97 + 32];
        g_dec[bn] = v;
        g_d[bn] = fsigmoid(v);
    }
    if (warp < BSZ) {
        int b = warp;
        size_t bn = (size_t)b*NN + n;
        float p0 = prim_in[bn*64 + lane]      + dlt[b*97 + 33 + lane];
        float p1 = prim_in[bn*64 + lane + 32] + dlt[b*97 + 33 + lane + 32];
        float ss = p0*p0 + p1*p1;
        #pragma unroll
        for (int off = 16; off; off >>= 1) ss += __shfl_xor_sync(0xffffffffu, ss, off);
        float sc = rsqrtf(ss*(1.f/64.f) + 1e-6f);
        g_prim[bn*64 + lane]      = p0*sc;
        g_prim[bn*64 + lane + 32] = p1*sc;
    }
}

// ================= state_const / msg_const (unchanged) =================
__global__ __launch_bounds__(256, 4)
void k_const(const float* __restrict__ sb1, const float* __restrict__ mb1_,
             const float* __restrict__ nid)
{
    __shared__ float xs[64*132];
    const int tid = threadIdx.x;
    const int r0 = blockIdx.x * 64;
    const int which = blockIdx.y;
    const float* WC = which ? g_WsC : g_WmC;
    const float* b1 = which ? sb1 : mb1_;
    float* outp     = which ? g_sconst : g_mconst;

    for (int i = tid; i < 64*132; i += 256) {
        int rr = i / 132, j = i - rr*132;
        size_t r = (size_t)(r0 + rr);
        int nn_ = (int)(r & (NN-1));
        float v = 0.f;
        if (j < 64)        v = g_prim[r*64 + j];
        else if (j < 128)  v = nid[(size_t)nn_*64 + (j-64)];
        else if (j == 128) v = g_dec[r];
        xs[i] = v;
    }
    __syncthreads();

    const int ty = tid >> 5, tx = tid & 31;
    float acc[8][8];
    #pragma unroll
    for (int i = 0; i < 8; i++)
        #pragma unroll
        for (int u = 0; u < 8; u++) acc[i][u] = 0.f;
    for (int j = 0; j < 129; ++j) {
        float a[8], w[8];
        #pragma unroll
        for (int i = 0; i < 8; i++) a[i] = xs[(ty*8+i)*132 + j];
        #pragma unroll
        for (int u = 0; u < 8; u++) w[u] = __ldg(WC + j*256 + tx + 32*u);
        #pragma unroll
        for (int i = 0; i < 8; i++)
            #pragma unroll
            for (int u = 0; u < 8; u++) acc[i][u] += a[i]*w[u];
    }
    #pragma unroll
    for (int i = 0; i < 8; i++) {
        int r = r0 + ty*8 + i;
        #pragma unroll
        for (int u = 0; u < 8; u++) {
            int c = tx + 32*u;
            outp[(size_t)r*256 + c] = acc[i][u] + __ldg(b1 + c);
        }
    }
}

// ================= fused step (warp-synchronous, mma.sync bf16x3) =================
// CTA = 64 rows, 128 threads (4 warps). Warp w owns rows 16w..16w+15.
// Per-warp smem: aH 16x72 bf16 | aL | hidH 16x264 bf16 | hidL  = 21504 B
#define A_STRIDE   144          // bytes per row (72 bf16)
#define H_STRIDE   528          // bytes per row (264 bf16)
#define AH_OFF     0
#define AL_OFF     2304
#define HH_OFF     4608
#define HL_OFF     13056
#define WARP_BYTES 21504
#define STEP_SMEM  (4*WARP_BYTES)

// wide GEMM: C[16x256] = A[16x64] @ W + const -> tanh -> hid (bf16 h/l in smem)
__device__ __forceinline__ void wide_phase(char* wmem, uint32_t wsm,
                                           const uint4* __restrict__ Wpk,
                                           const float* __restrict__ cstW, int ln)
{
    uint32_t Ah[4][4], Al[4][4];
    const int row = ln & 15;
    const uint32_t coff = (uint32_t)((ln >> 4) << 4);
    #pragma unroll
    for (int kt = 0; kt < 4; kt++) {
        uint32_t ad = wsm + AH_OFF + row*A_STRIDE + kt*32 + coff;
        ldm_x4(Ah[kt], ad);
        ldm_x4(Al[kt], ad + (AL_OFF - AH_OFF));
    }
    const int g = ln >> 2, q = ln & 3;
    #pragma unroll 2
    for (int nt = 0; nt < 32; ++nt) {
        float d[4] = {0.f, 0.f, 0.f, 0.f};
        #pragma unroll
        for (int kt = 0; kt < 4; ++kt) {
            uint4 u = __ldg(Wpk + (size_t)(kt*32 + nt)*32 + ln);
            mma_bf16(d, Ah[kt], u.x, u.y);
            mma_bf16(d, Ah[kt], u.z, u.w);
            mma_bf16(d, Al[kt], u.x, u.y);
        }
        int c0 = nt*8 + q*2;
        float2 cA = *(const float2*)(cstW + (size_t)g*256 + c0);
        float2 cB = *(const float2*)(cstW + (size_t)(g+8)*256 + c0);
        float h0 = ftanh(d[0] + cA.x), h1 = ftanh(d[1] + cA.y);
        float h2 = ftanh(d[2] + cB.x), h3 = ftanh(d[3] + cB.y);
        uint32_t hi0, lo0, hi1, lo1;
        split2(h0, h1, hi0, lo0);
        split2(h2, h3, hi1, lo1);
        *(uint32_t*)(wmem + HH_OFF + g*H_STRIDE + c0*2)     = hi0;
        *(uint32_t*)(wmem + HL_OFF + g*H_STRIDE + c0*2)     = lo0;
        *(uint32_t*)(wmem + HH_OFF + (g+8)*H_STRIDE + c0*2) = hi1;
        *(uint32_t*)(wmem + HL_OFF + (g+8)*H_STRIDE + c0*2) = lo1;
    }
}

// narrow GEMM: acc[8 ntiles][4] = hid[16x256] @ W[256x64]
__device__ __forceinline__ void narrow_gemm(uint32_t wsm,
                                            const uint4* __restrict__ Wpk,
                                            int ln, float d[8][4])
{
    #pragma unroll
    for (int nt = 0; nt < 8; nt++)
        #pragma unroll
        for (int i = 0; i < 4; i++) d[nt][i] = 0.f;
    const int row = ln & 15;
    const uint32_t coff = (uint32_t)((ln >> 4) << 4);
    #pragma unroll 2
    for (int kt = 0; kt < 16; ++kt) {
        uint32_t Ah[4], Al[4];
        uint32_t ad = wsm + HH_OFF + row*H_STRIDE + kt*32 + coff;
        ldm_x4(Ah, ad);
        ldm_x4(Al, ad + (HL_OFF - HH_OFF));
        #pragma unroll
        for (int nt = 0; nt < 8; ++nt) {
            uint4 u = __ldg(Wpk + (size_t)(kt*8 + nt)*32 + ln);
            mma_bf16(d[nt], Ah, u.x, u.y);
            mma_bf16(d[nt], Ah, u.z, u.w);
            mma_bf16(d[nt], Al, u.x, u.y);
        }
    }
}

__global__ __launch_bounds__(128, 2)
void k_step(int t, const float* __restrict__ cc, const int* __restrict__ conn,
            const float* __restrict__ nid, const float* __restrict__ sb2,
            const float* __restrict__ mb2, float* __restrict__ out)
{
    extern __shared__ char smem[];
    const int tid = threadIdx.x;
    const int w   = tid >> 5, ln = tid & 31;
    char*    wmem = smem + w*WARP_BYTES;
    const uint32_t wsm = smem_u32(smem) + w*WARP_BYTES;

    const int b     = blockIdx.y;
    const int ntblk = blockIdx.x;
    const int n0    = ntblk*64;
    const int nfirst = n0 + w*16;
    const int sel   = t & 1;
    const size_t growbase = (size_t)b*NN + nfirst;

    // ---- phase 0: gather (+inject) -> bf16 h/l into s_a ----
    {
        const u64*    mq  = (const u64*)g_msg2[sel] + (size_t)b*NN*32;
        const int4*   cn4 = (const int4*)conn;
        const float4* ws4 = (const float4*)g_wsig4;
        #pragma unroll 1
        for (int g = 0; g < 16; ++g) {
            const int n = nfirst + g;
            const size_t cb = (size_t)n*8;
            const size_t wb = ((size_t)b*NN + n)*8;
            u64 a0 = 0ull, a1 = 0ull;
            #pragma unroll
            for (int kq = 0; kq < 8; ++kq) {
                int4   id = __ldg(cn4 + cb + kq);
                float4 wt = __ldg(ws4 + wb + kq);
                ffma2(a0, pack2(wt.x), mq[(size_t)id.x*32 + ln]);
                ffma2(a1, pack2(wt.y), mq[(size_t)id.y*32 + ln]);
                ffma2(a0, pack2(wt.z), mq[(size_t)id.z*32 + ln]);
                ffma2(a1, pack2(wt.w), mq[(size_t)id.w*32 + ln]);
            }
            float2 v0 = unpack2(a0), v1 = unpack2(a1);
            float x0 = v0.x + v1.x, x1 = v0.y + v1.y;
            if ((n & 127) < 4) {
                float2 cv = *(const float2*)(cc + ((size_t)b*TT + t)*2048 + (n>>7)*64 + ln*2);
                x0 += cv.x; x1 += cv.y;
            }
            uint32_t hi, lo;
            split2(x0, x1, hi, lo);
            *(uint32_t*)(wmem + AH_OFF + g*A_STRIDE + ln*4) = hi;
            *(uint32_t*)(wmem + AL_OFF + g*A_STRIDE + ln*4) = lo;
        }
    }
    __syncwarp();

    // ---- phase 1: hid = tanh(recv @ Wsi + state_const) ----
    wide_phase(wmem, wsm, g_Wpk, g_sconst + growbase*256, ln);
    __syncwarp();

    // ---- phase 2: upd = tanh(hid @ Ws2 + sb2); h = d*h + (1-d)*upd -> s_a ----
    {
        float d[8][4];
        narrow_gemm(wsm, g_Wpk + 4096, ln, d);
        const int g = ln >> 2, q = ln & 3;
        #pragma unroll
        for (int nt = 0; nt < 8; ++nt) {
            int c0 = nt*8 + q*2;
            float2 bb = *(const float2*)(sb2 + c0);
            // row g
            {
                size_t grow = growbase + g;
                float dv = g_d[grow];
                float2 ho = g_h2[grow*32 + (c0 >> 1)];
                float u0 = ftanh(d[nt][0] + bb.x), u1 = ftanh(d[nt][1] + bb.y);
                float hv0 = dv*ho.x + (1.f-dv)*u0, hv1 = dv*ho.y + (1.f-dv)*u1;
                g_h2[grow*32 + (c0 >> 1)] = make_float2(hv0, hv1);
                uint32_t hi, lo; split2(hv0, hv1, hi, lo);
                *(uint32_t*)(wmem + AH_OFF + g*A_STRIDE + c0*2) = hi;
                *(uint32_t*)(wmem + AL_OFF + g*A_STRIDE + c0*2) = lo;
            }
            // row g+8
            {
                size_t grow = growbase + g + 8;
                float dv = g_d[grow];
                float2 ho = g_h2[grow*32 + (c0 >> 1)];
                float u0 = ftanh(d[nt][2] + bb.x), u1 = ftanh(d[nt][3] + bb.y);
                float hv0 = dv*ho.x + (1.f-dv)*u0, hv1 = dv*ho.y + (1.f-dv)*u1;
                g_h2[grow*32 + (c0 >> 1)] = make_float2(hv0, hv1);
                uint32_t hi, lo; split2(hv0, hv1, hi, lo);
                *(uint32_t*)(wmem + AH_OFF + (g+8)*A_STRIDE + c0*2) = hi;
                *(uint32_t*)(wmem + AL_OFF + (g+8)*A_STRIDE + c0*2) = lo;
            }
        }
    }
    __syncwarp();

    // ---- phase 3: mh = tanh(h @ Wmh + msg_const) ----
    wide_phase(wmem, wsm, g_Wpk + 2*4096, g_mconst + growbase*256, ln);
    __syncwarp();

    // ---- phase 4: msg = tanh(mh @ Wm2 + mb2) + nid; readout ----
    {
        float d[8][4];
        narrow_gemm(wsm, g_Wpk + 3*4096, ln, d);
        const int g = ln >> 2, q = ln & 3;
        const int roflag = (ntblk & 1) && (w == 3);
        float2* msgout = g_msg2[sel ^ 1];
        float* s_ro = (float*)(wmem + AH_OFF);   // s_a region, free now
        #pragma unroll
        for (int nt = 0; nt < 8; ++nt) {
            int c0 = nt*8 + q*2;
            float2 bb = *(const float2*)(mb2 + c0);
            // row g
            {
                int n = nfirst + g;
                size_t grow = growbase + g;
                float2 nv = *(const float2*)(nid + (size_t)n*64 + c0);
                float m0 = ftanh(d[nt][0] + bb.x) + nv.x;
                float m1 = ftanh(d[nt][1] + bb.y) + nv.y;
                msgout[grow*32 + (c0 >> 1)] = make_float2(m0, m1);
            }
            // row g+8
            {
                int n = nfirst + g + 8;
                size_t grow = growbase + g + 8;
                float2 nv = *(const float2*)(nid + (size_t)n*64 + c0);
                float m0 = ftanh(d[nt][2] + bb.x) + nv.x;
                float m1 = ftanh(d[nt][3] + bb.y) + nv.y;
                msgout[grow*32 + (c0 >> 1)] = make_float2(m0, m1);
                if (roflag && g >= 4)
                    *(float2*)(s_ro + (g-4)*64 + c0) = make_float2(m0, m1);
            }
        }
        __syncwarp();
        if (roflag) {
            size_t obase = ((size_t)b*TT + t)*2048 + (ntblk >> 1)*64;
            float v0 = 0.25f*(s_ro[ln]      + s_ro[64+ln]  + s_ro[128+ln] + s_ro[192+ln]);
            float v1 = 0.25f*(s_ro[32+ln]   + s_ro[96+ln]  + s_ro[160+ln] + s_ro[224+ln]);
            out[obase + ln]      = v0;
            out[obase + 32 + ln] = v1;
        }
    }
}

// ================= launcher =================
extern "C" void kernel_launch(void* const* d_in, const int* in_sizes, int n_in,
                              void* d_out, int out_size)
{
    const float* cc      = (const float*)d_in[0];
    const float* h_in    = (const float*)d_in[1];
    const float* msg_in  = (const float*)d_in[2];
    const float* wconn   = (const float*)d_in[3];
    const float* declog  = (const float*)d_in[4];
    const float* prim_in = (const float*)d_in[5];
    const float* heb     = (const float*)d_in[6];
    const float* sw1     = (const float*)d_in[7];
    const float* sb1     = (const float*)d_in[8];
    const float* sw2     = (const float*)d_in[9];
    const float* sb2     = (const float*)d_in[10];
    const float* mw1     = (const float*)d_in[11];
    const float* mb1     = (const float*)d_in[12];
    const float* mw2     = (const float*)d_in[13];
    const float* mb2     = (const float*)d_in[14];
    const float* modw1   = (const float*)d_in[15];
    const float* modb1   = (const float*)d_in[16];
    const float* modw2   = (const float*)d_in[17];
    const float* modb2   = (const float*)d_in[18];
    const float* nid     = (const float*)d_in[19];
    const int*   conn    = (const int*)d_in[20];
    float* out = (float*)d_out;

    cudaFuncSetAttribute(k_step, cudaFuncAttributeMaxDynamicSharedMemorySize, STEP_SMEM);

    k_init<<<256, 256>>>(h_in, msg_in, sw1, sw2, mw1, mw2);
    k_mod<<<NN, 256>>>(h_in, heb, declog, prim_in, wconn,
                       modw1, modb1, modw2, modb2, nid);
    k_const<<<dim3(512, 2), 256>>>(sb1, mb1, nid);

    for (int t = 0; t < TT; ++t) {
        k_step<<<dim3(NN/64, BSZ), 128, STEP_SMEM>>>(t, cc, conn, nid, sb2, mb2, out);
    }
}

// round 11
// speedup vs baseline: 1.4231x; 1.0710x over previous
#include <cuda_runtime.h>
#include <math.h>
#include <stdint.h>

#define NN   4096
#define KK   32
#define DD   64
#define BSZ  8
#define TT   32
#define HSZ  256
#define ROWS (BSZ*NN)

typedef unsigned long long u64;

// ================= persistent device scratch =================
__device__ float4 g_wsig4[ROWS*KK/4];
__device__ float  g_d[ROWS];
__device__ float  g_dec[ROWS];
__device__ float  g_prim[ROWS*DD];
__device__ float  g_sconst[(size_t)ROWS*HSZ];   // [row][256]
__device__ float  g_mconst[(size_t)ROWS*HSZ];
__device__ float2 g_h2[ROWS*DD/2];              // [row][32 float2]
__device__ float2 g_msg2[2][ROWS*DD/2];
__device__ float  g_WsC[129*HSZ];               // const-GEMM weights [j][h]
__device__ float  g_WmC[129*HSZ];
// fragment-packed bf16 weights: phase p*4096 .. : uint4 = {b0h,b1h,b0l,b1l}
// p0 = Wsi (wide 64x256), p1 = Ws2 (narrow 256x64), p2 = Wmh, p3 = Wm2
__device__ uint4  g_Wpk[4*4096];

// ================= helpers =================
__device__ __forceinline__ float ftanh(float x) {
    float ax = fabsf(x);
    float e  = __expf(-2.f*ax);
    float t  = __fdividef(1.f - e, 1.f + e);
    return copysignf(t, x);
}
__device__ __forceinline__ float fsigmoid(float x) {
    return __fdividef(1.f, 1.f + __expf(-x));
}
__device__ __forceinline__ u64 pack2(float x) {
    u64 r; unsigned xi = __float_as_uint(x);
    asm("mov.b64 %0, {%1,%1};" : "=l"(r) : "r"(xi));
    return r;
}
__device__ __forceinline__ float2 unpack2(u64 v) {
    unsigned lo, hi;
    asm("mov.b64 {%0,%1}, %2;" : "=r"(lo), "=r"(hi) : "l"(v));
    return make_float2(__uint_as_float(lo), __uint_as_float(hi));
}
__device__ __forceinline__ void ffma2(u64& d, u64 a, u64 b) {
    asm("fma.rn.f32x2 %0, %1, %2, %0;" : "+l"(d) : "l"(a), "l"(b));
}
// split (a,b) into bf16 hi-pair and lo-pair; lower 16 bits = a
__device__ __forceinline__ void split2(float a, float b, uint32_t& hi, uint32_t& lo) {
    uint32_t h;
    asm("cvt.rn.bf16x2.f32 %0, %1, %2;" : "=r"(h) : "f"(b), "f"(a));
    float ra = a - __uint_as_float(h << 16);
    float rb = b - __uint_as_float(h & 0xffff0000u);
    uint32_t l;
    asm("cvt.rn.bf16x2.f32 %0, %1, %2;" : "=r"(l) : "f"(rb), "f"(ra));
    hi = h; lo = l;
}
__device__ __forceinline__ void ldm_x4(uint32_t* r, uint32_t addr) {
    asm volatile("ldmatrix.sync.aligned.m8n8.x4.shared.b16 {%0,%1,%2,%3}, [%4];"
        : "=r"(r[0]), "=r"(r[1]), "=r"(r[2]), "=r"(r[3]) : "r"(addr));
}
__device__ __forceinline__ void mma_bf16(float* d, const uint32_t* a,
                                         uint32_t b0, uint32_t b1) {
    asm volatile("mma.sync.aligned.m16n8k16.row.col.f32.bf16.bf16.f32 "
        "{%0,%1,%2,%3}, {%4,%5,%6,%7}, {%8,%9}, {%0,%1,%2,%3};"
        : "+f"(d[0]), "+f"(d[1]), "+f"(d[2]), "+f"(d[3])
        : "r"(a[0]), "r"(a[1]), "r"(a[2]), "r"(a[3]), "r"(b0), "r"(b1));
}
__device__ __forceinline__ uint32_t smem_u32(const void* p) {
    uint32_t a;
    asm("{ .reg .u64 t; cvta.to.shared.u64 t, %1; cvt.u32.u64 %0, t; }"
        : "=r"(a) : "l"(p));
    return a;
}

// ================= init: copy state, build const-W, pack mma weights =================
__global__ void k_init(const float* __restrict__ h_in, const float* __restrict__ msg_in,
                       const float* __restrict__ sw1, const float* __restrict__ sw2,
                       const float* __restrict__ mw1, const float* __restrict__ mw2)
{
    int i0 = blockIdx.x*blockDim.x + threadIdx.x;
    int stride = gridDim.x*blockDim.x;
    float* gh  = (float*)g_h2;
    float* gm0 = (float*)g_msg2[0];
    for (int i = i0; i < ROWS*DD; i += stride) { gh[i] = h_in[i]; gm0[i] = msg_in[i]; }
    for (int i = i0; i < 129*HSZ; i += stride) {
        int j = i >> 8, h = i & 255;
        g_WsC[i] = (j < 128) ? sw1[h*193 + 64 + j] : sw1[h*193 + 192];
        g_WmC[i] = (j < 128) ? mw1[h*192 + 64 + j] : 0.f;
    }
    for (int e = i0; e < 4*4096; e += stride) {
        int p = e >> 12, r = e & 4095;
        int lane = r & 31, q = r >> 5;
        int NT = (p == 0 || p == 2) ? 32 : 8;
        int kt = q / NT, nt = q - kt*NT;
        int k0 = kt*16 + (lane & 3)*2;
        int n  = nt*8 + (lane >> 2);
        float w00, w01, w10, w11;
        if (p == 0)      { const float* s = sw1 + (size_t)n*193;
                           w00 = s[k0]; w01 = s[k0+1]; w10 = s[k0+8]; w11 = s[k0+9]; }
        else if (p == 1) { const float* s = sw2 + (size_t)n*256;
                           w00 = s[k0]; w01 = s[k0+1]; w10 = s[k0+8]; w11 = s[k0+9]; }
        else if (p == 2) { const float* s = mw1 + (size_t)n*192;
                           w00 = s[k0]; w01 = s[k0+1]; w10 = s[k0+8]; w11 = s[k0+9]; }
        else             { const float* s = mw2 + (size_t)n*256;
                           w00 = s[k0]; w01 = s[k0+1]; w10 = s[k0+8]; w11 = s[k0+9]; }
        uint32_t b0h, b0l, b1h, b1l;
        split2(w00, w01, b0h, b0l);
        split2(w10, w11, b1h, b1l);
        g_Wpk[e] = make_uint4(b0h, b1h, b0l, b1l);
    }
}

// ================= per-neuron modulation MLP (unchanged) =================
__global__ void k_mod(const float* __restrict__ h_in, const float* __restrict__ heb,
                      const float* __restrict__ dec_in, const float* __restrict__ prim_in,
                      const float* __restrict__ wconn_in,
                      const float* __restrict__ mw1, const float* __restrict__ mb1,
                      const float* __restrict__ mw2, const float* __restrict__ mb2,
                      const float* __restrict__ nid)
{
    const int n = blockIdx.x;
    const int tid = threadIdx.x;
    const int warp = tid >> 5, lane = tid & 31;
    __shared__ float xs[BSZ*225];
    __shared__ float hid[BSZ*64];
    __shared__ float dlt[BSZ*97];

    for (int i = tid; i < BSZ*225; i += 256) {
        int b = i / 225, j = i - b*225;
        size_t bn = (size_t)b*NN + n;
        float v;
        if (j < 32)        v = heb[bn*32 + j];
        else if (j < 96)   v = h_in[bn*64 + (j-32)];
        else if (j == 96)  v = dec_in[bn];
        else if (j < 161)  v = prim_in[bn*64 + (j-97)];
        else               v = nid[(size_t)n*64 + (j-161)];
        xs[i] = v;
    }
    __syncthreads();

    const float* w1 = mw1 + (size_t)n*64*225;
    for (int hh = warp; hh < 64; hh += 8) {
        float acc[BSZ];
        #pragma unroll
        for (int b = 0; b < BSZ; b++) acc[b] = 0.f;
        for (int j = lane; j < 225; j += 32) {
            float w = w1[hh*225 + j];
            #pragma unroll
            for (int b = 0; b < BSZ; b++) acc[b] += w * xs[b*225 + j];
        }
        #pragma unroll
        for (int off = 16; off; off >>= 1) {
            #pragma unroll
            for (int b = 0; b < BSZ; b++) acc[b] += __shfl_xor_sync(0xffffffffu, acc[b], off);
        }
        if (lane == 0) {
            float bb = mb1[(size_t)n*64 + hh];
            #pragma unroll
            for (int b = 0; b < BSZ; b++) hid[b*64 + hh] = ftanh(acc[b] + bb);
        }
    }
    __syncthreads();

    const float* w2 = mw2 + (size_t)n*64*97;
    for (int o = warp; o < 97; o += 8) {
        float acc[BSZ];
        #pragma unroll
        for (int b = 0; b < BSZ; b++) acc[b] = 0.f;
        #pragma unroll
        for (int j2 = 0; j2 < 2; ++j2) {
            int j = lane + 32*j2;
            float w = w2[(size_t)j*97 + o];
            #pragma unroll
            for (int b = 0; b < BSZ; b++) acc[b] += w * hid[b*64 + j];
        }
        #pragma unroll
        for (int off = 16; off; off >>= 1) {
            #pragma unroll
            for (int b = 0; b < BSZ; b++) acc[b] += __shfl_xor_sync(0xffffffffu, acc[b], off);
        }
        if (lane == 0) {
            float bb = mb2[(size_t)n*97 + o];
            #pragma unroll
            for (int b = 0; b < BSZ; b++) dlt[b*97 + o] = acc[b] + bb;
        }
    }
    __syncthreads();

    float* wsig = (float*)g_wsig4;
    for (int i = tid; i < BSZ*KK; i += 256) {
        int b = i >> 5, k = i & 31;
        size_t bn = (size_t)b*NN + n;
        wsig[bn*32 + k] = fsigmoid(wconn_in[bn*32 + k] + dlt[b*97 + k]);
    }
    if (tid < BSZ) {
        size_t bn = (size_t)tid*NN + n;
        float v = dec_in[bn] + dlt[tid*97 + 32];
        g_dec[bn] = v;
        g_d[bn] = fsigmoid(v);
    }
    if (warp < BSZ) {
        int b = warp;
        size_t bn = (size_t)b*NN + n;
        float p0 = prim_in[bn*64 + lane]      + dlt[b*97 + 33 + lane];
        float p1 = prim_in[bn*64 + lane + 32] + dlt[b*97 + 33 + lane + 32];
        float ss = p0*p0 + p1*p1;
        #pragma unroll
        for (int off = 16; off; off >>= 1) ss += __shfl_xor_sync(0xffffffffu, ss, off);
        float sc = rsqrtf(ss*(1.f/64.f) + 1e-6f);
        g_prim[bn*64 + lane]      = p0*sc;
        g_prim[bn*64 + lane + 32] = p1*sc;
    }
}

// ================= state_const / msg_const (unchanged) =================
__global__ __launch_bounds__(256, 4)
void k_const(const float* __restrict__ sb1, const float* __restrict__ mb1_,
             const float* __restrict__ nid)
{
    __shared__ float xs[64*132];
    const int tid = threadIdx.x;
    const int r0 = blockIdx.x * 64;
    const int which = blockIdx.y;
    const float* WC = which ? g_WsC : g_WmC;
    const float* b1 = which ? sb1 : mb1_;
    float* outp     = which ? g_sconst : g_mconst;

    for (int i = tid; i < 64*132; i += 256) {
        int rr = i / 132, j = i - rr*132;
        size_t r = (size_t)(r0 + rr);
        int nn_ = (int)(r & (NN-1));
        float v = 0.f;
        if (j < 64)        v = g_prim[r*64 + j];
        else if (j < 128)  v = nid[(size_t)nn_*64 + (j-64)];
        else if (j == 128) v = g_dec[r];
        xs[i] = v;
    }
    __syncthreads();

    const int ty = tid >> 5, tx = tid & 31;
    float acc[8][8];
    #pragma unroll
    for (int i = 0; i < 8; i++)
        #pragma unroll
        for (int u = 0; u < 8; u++) acc[i][u] = 0.f;
    for (int j = 0; j < 129; ++j) {
        float a[8], w[8];
        #pragma unroll
        for (int i = 0; i < 8; i++) a[i] = xs[(ty*8+i)*132 + j];
        #pragma unroll
        for (int u = 0; u < 8; u++) w[u] = __ldg(WC + j*256 + tx + 32*u);
        #pragma unroll
        for (int i = 0; i < 8; i++)
            #pragma unroll
            for (int u = 0; u < 8; u++) acc[i][u] += a[i]*w[u];
    }
    #pragma unroll
    for (int i = 0; i < 8; i++) {
        int r = r0 + ty*8 + i;
        #pragma unroll
        for (int u = 0; u < 8; u++) {
            int c = tx + 32*u;
            outp[(size_t)r*256 + c] = acc[i][u] + __ldg(b1 + c);
        }
    }
}

// ================= fused wide->tanh->narrow, all in registers =================
// Ah/Al: A-frags of the 16x64 input (4 k-chunks). nacc: narrow D accum (8 n-tiles).
// Wide D frag (rows gr,gr+8; cols nt*8+2q) converts directly to narrow A frag regs.
__device__ __forceinline__ void fused_wide_narrow(
    const uint32_t Ah[4][4], const uint32_t Al[4][4],
    const uint4* __restrict__ Wwide, const uint4* __restrict__ Wnarrow,
    const float* __restrict__ cst, int ln, float nacc[8][4])
{
    const int gr = ln >> 2, q = ln & 3;
    #pragma unroll
    for (int nt = 0; nt < 8; nt++)
        #pragma unroll
        for (int i = 0; i < 4; i++) nacc[nt][i] = 0.f;

    #pragma unroll 2
    for (int kt = 0; kt < 16; ++kt) {
        uint32_t ah[4], al[4];   // hid A-frag for this 16-col chunk
        #pragma unroll
        for (int half = 0; half < 2; ++half) {
            const int nt = 2*kt + half;
            float d[4] = {0.f, 0.f, 0.f, 0.f};
            #pragma unroll
            for (int wk = 0; wk < 4; ++wk) {
                uint4 u = __ldg(Wwide + (size_t)(wk*32 + nt)*32 + ln);
                mma_bf16(d, Ah[wk], u.x, u.y);
                mma_bf16(d, Ah[wk], u.z, u.w);
                mma_bf16(d, Al[wk], u.x, u.y);
            }
            const int c0 = nt*8 + q*2;
            float2 cA = *(const float2*)(cst + (size_t)gr*256 + c0);
            float2 cB = *(const float2*)(cst + (size_t)(gr+8)*256 + c0);
            float h0 = ftanh(d[0] + cA.x), h1 = ftanh(d[1] + cA.y);
            float h2 = ftanh(d[2] + cB.x), h3 = ftanh(d[3] + cB.y);
            split2(h0, h1, ah[half*2],   al[half*2]);     // rows gr,   k-block half
            split2(h2, h3, ah[half*2+1], al[half*2+1]);   // rows gr+8, k-block half
        }
        #pragma unroll
        for (int nt = 0; nt < 8; ++nt) {
            uint4 u = __ldg(Wnarrow + (size_t)(kt*8 + nt)*32 + ln);
            mma_bf16(nacc[nt], ah, u.x, u.y);
            mma_bf16(nacc[nt], ah, u.z, u.w);
            mma_bf16(nacc[nt], al, u.x, u.y);
        }
    }
}

// ================= fused step: gather -> (wide+narrow)x2, register-chained =================
// CTA = 64 rows, 128 threads (4 warps). Warp w owns rows 16w..16w+15.
// smem per warp: gather A-tile hi/lo only (16x72 bf16 x2 = 4608 B)
#define A_STRIDE   144
#define AH_OFF     0
#define AL_OFF     2304
#define WARP_BYTES 4608
#define STEP_SMEM  (4*WARP_BYTES)

__global__ __launch_bounds__(128, 3)
void k_step(int t, const float* __restrict__ cc, const int* __restrict__ conn,
            const float* __restrict__ nid, const float* __restrict__ sb2,
            const float* __restrict__ mb2, float* __restrict__ out)
{
    extern __shared__ char smem[];
    const int tid = threadIdx.x;
    const int w   = tid >> 5, ln = tid & 31;
    char*    wmem = smem + w*WARP_BYTES;
    const uint32_t wsm = smem_u32(smem) + w*WARP_BYTES;

    const int b      = blockIdx.y;
    const int ntblk  = blockIdx.x;
    const int n0     = ntblk*64;
    const int nfirst = n0 + w*16;
    const int sel    = t & 1;
    const size_t growbase = (size_t)b*NN + nfirst;

    // ---- phase 0: gather (+inject) -> bf16 h/l A-tile in smem ----
    {
        const u64*    mq  = (const u64*)g_msg2[sel] + (size_t)b*NN*32;
        const int4*   cn4 = (const int4*)conn;
        const float4* ws4 = (const float4*)g_wsig4;
        #pragma unroll 1
        for (int g = 0; g < 16; ++g) {
            const int n = nfirst + g;
            const size_t cb = (size_t)n*8;
            const size_t wb = ((size_t)b*NN + n)*8;
            u64 a0 = 0ull, a1 = 0ull;
            #pragma unroll
            for (int kq = 0; kq < 8; ++kq) {
                int4   id = __ldg(cn4 + cb + kq);
                float4 wt = __ldg(ws4 + wb + kq);
                ffma2(a0, pack2(wt.x), mq[(size_t)id.x*32 + ln]);
                ffma2(a1, pack2(wt.y), mq[(size_t)id.y*32 + ln]);
                ffma2(a0, pack2(wt.z), mq[(size_t)id.z*32 + ln]);
                ffma2(a1, pack2(wt.w), mq[(size_t)id.w*32 + ln]);
            }
            float2 v0 = unpack2(a0), v1 = unpack2(a1);
            float x0 = v0.x + v1.x, x1 = v0.y + v1.y;
            if ((n & 127) < 4) {
                float2 cv = *(const float2*)(cc + ((size_t)b*TT + t)*2048 + (n>>7)*64 + ln*2);
                x0 += cv.x; x1 += cv.y;
            }
            uint32_t hi, lo;
            split2(x0, x1, hi, lo);
            *(uint32_t*)(wmem + AH_OFF + g*A_STRIDE + ln*4) = hi;
            *(uint32_t*)(wmem + AL_OFF + g*A_STRIDE + ln*4) = lo;
        }
    }
    __syncwarp();

    // load gather A-frags once; smem A region free afterwards
    uint32_t Ah[4][4], Al[4][4];
    {
        const int row = ln & 15;
        const uint32_t coff = (uint32_t)((ln >> 4) << 4);
        #pragma unroll
        for (int kt = 0; kt < 4; kt++) {
            uint32_t ad = wsm + AH_OFF + row*A_STRIDE + kt*32 + coff;
            ldm_x4(Ah[kt], ad);
            ldm_x4(Al[kt], ad + (AL_OFF - AH_OFF));
        }
    }
    __syncwarp();

    const int gr = ln >> 2, q = ln & 3;
    float nacc[8][4];

    // ---- phases 1+2: hid = tanh(recv@Wsi + sconst); nacc = hid@Ws2 ----
    fused_wide_narrow(Ah, Al, g_Wpk, g_Wpk + 4096,
                      g_sconst + growbase*256, ln, nacc);

    // ---- phase 2 epilogue: h update; build phase-3 A-frags in regs ----
    uint32_t Hh[4][4], Hl[4][4];
    {
        const float dv0 = g_d[growbase + gr];
        const float dv1 = g_d[growbase + gr + 8];
        #pragma unroll
        for (int nt = 0; nt < 8; ++nt) {
            const int c0 = nt*8 + q*2;
            float2 bb = *(const float2*)(sb2 + c0);
            // row gr
            {
                size_t grow = growbase + gr;
                float2 ho = g_h2[grow*32 + (c0 >> 1)];
                float u0 = ftanh(nacc[nt][0] + bb.x), u1 = ftanh(nacc[nt][1] + bb.y);
                float hv0 = dv0*ho.x + (1.f-dv0)*u0, hv1 = dv0*ho.y + (1.f-dv0)*u1;
                g_h2[grow*32 + (c0 >> 1)] = make_float2(hv0, hv1);
                split2(hv0, hv1, Hh[nt>>1][(nt&1)*2], Hl[nt>>1][(nt&1)*2]);
            }
            // row gr+8
            {
                size_t grow = growbase + gr + 8;
                float2 ho = g_h2[grow*32 + (c0 >> 1)];
                float u0 = ftanh(nacc[nt][2] + bb.x), u1 = ftanh(nacc[nt][3] + bb.y);
                float hv0 = dv1*ho.x + (1.f-dv1)*u0, hv1 = dv1*ho.y + (1.f-dv1)*u1;
                g_h2[grow*32 + (c0 >> 1)] = make_float2(hv0, hv1);
                split2(hv0, hv1, Hh[nt>>1][(nt&1)*2+1], Hl[nt>>1][(nt&1)*2+1]);
            }
        }
    }

    // ---- phases 3+4: mh = tanh(h@Wmh + mconst); nacc = mh@Wm2 ----
    fused_wide_narrow(Hh, Hl, g_Wpk + 2*4096, g_Wpk + 3*4096,
                      g_mconst + growbase*256, ln, nacc);

    // ---- phase 4 epilogue: msg = tanh(.+mb2)+nid; readout ----
    {
        const int roflag = (ntblk & 1) && (w == 3);
        float2* msgout = g_msg2[sel ^ 1];
        float* s_ro = (float*)wmem;      // gather A region, free now
        #pragma unroll
        for (int nt = 0; nt < 8; ++nt) {
            const int c0 = nt*8 + q*2;
            float2 bb = *(const float2*)(mb2 + c0);
            // row gr
            {
                int n = nfirst + gr;
                size_t grow = growbase + gr;
                float2 nv = *(const float2*)(nid + (size_t)n*64 + c0);
                float m0 = ftanh(nacc[nt][0] + bb.x) + nv.x;
                float m1 = ftanh(nacc[nt][1] + bb.y) + nv.y;
                msgout[grow*32 + (c0 >> 1)] = make_float2(m0, m1);
            }
            // row gr+8
            {
                int n = nfirst + gr + 8;
                size_t grow = growbase + gr + 8;
                float2 nv = *(const float2*)(nid + (size_t)n*64 + c0);
                float m0 = ftanh(nacc[nt][2] + bb.x) + nv.x;
                float m1 = ftanh(nacc[nt][3] + bb.y) + nv.y;
                msgout[grow*32 + (c0 >> 1)] = make_float2(m0, m1);
                if (roflag && gr >= 4)
                    *(float2*)(s_ro + (gr-4)*64 + c0) = make_float2(m0, m1);
            }
        }
        __syncwarp();
        if (roflag) {
            size_t obase = ((size_t)b*TT + t)*2048 + (ntblk >> 1)*64;
            float v0 = 0.25f*(s_ro[ln]      + s_ro[64+ln]  + s_ro[128+ln] + s_ro[192+ln]);
            float v1 = 0.25f*(s_ro[32+ln]   + s_ro[96+ln]  + s_ro[160+ln] + s_ro[224+ln]);
            out[obase + ln]      = v0;
            out[obase + 32 + ln] = v1;
        }
    }
}

// ================= launcher =================
extern "C" void kernel_launch(void* const* d_in, const int* in_sizes, int n_in,
                              void* d_out, int out_size)
{
    const float* cc      = (const float*)d_in[0];
    const float* h_in    = (const float*)d_in[1];
    const float* msg_in  = (const float*)d_in[2];
    const float* wconn   = (const float*)d_in[3];
    const float* declog  = (const float*)d_in[4];
    const float* prim_in = (const float*)d_in[5];
    const float* heb     = (const float*)d_in[6];
    const float* sw1     = (const float*)d_in[7];
    const float* sb1     = (const float*)d_in[8];
    const float* sw2     = (const float*)d_in[9];
    const float* sb2     = (const float*)d_in[10];
    const float* mw1     = (const float*)d_in[11];
    const float* mb1     = (const float*)d_in[12];
    const float* mw2     = (const float*)d_in[13];
    const float* mb2     = (const float*)d_in[14];
    const float* modw1   = (const float*)d_in[15];
    const float* modb1   = (const float*)d_in[16];
    const float* modw2   = (const float*)d_in[17];
    const float* modb2   = (const float*)d_in[18];
    const float* nid     = (const float*)d_in[19];
    const int*   conn    = (const int*)d_in[20];
    float* out = (float*)d_out;

    cudaFuncSetAttribute(k_step, cudaFuncAttributeMaxDynamicSharedMemorySize, STEP_SMEM);

    k_init<<<256, 256>>>(h_in, msg_in, sw1, sw2, mw1, mw2);
    k_mod<<<NN, 256>>>(h_in, heb, declog, prim_in, wconn,
                       modw1, modb1, modw2, modb2, nid);
    k_const<<<dim3(512, 2), 256>>>(sb1, mb1, nid);

    for (int t = 0; t < TT; ++t) {
        k_step<<<dim3(NN/64, BSZ), 128, STEP_SMEM>>>(t, cc, conn, nid, sb2, mb2, out);
    }
}

// round 12
// speedup vs baseline: 1.4586x; 1.0250x over previous
#include <cuda_runtime.h>
#include <math.h>
#include <stdint.h>

#define NN   4096
#define KK   32
#define DD   64
#define BSZ  8
#define TT   32
#define HSZ  256
#define ROWS (BSZ*NN)

typedef unsigned long long u64;

// ================= persistent device scratch =================
__device__ float4 g_wsig4[ROWS*KK/4];
__device__ float  g_d[ROWS];
__device__ float  g_dec[ROWS];
__device__ float  g_prim[ROWS*DD];
__device__ float  g_sconst[(size_t)ROWS*HSZ];   // [row][256]
__device__ float  g_mconst[(size_t)ROWS*HSZ];
__device__ float2 g_h2[ROWS*DD/2];              // [row][32 float2]
__device__ float2 g_msg2[2][ROWS*DD/2];
__device__ float  g_WsC[129*HSZ];               // const-GEMM weights [j][h]
__device__ float  g_WmC[129*HSZ];
// fragment-packed bf16 weights: phase p*4096 .. : uint4 = {b0h,b1h,b0l,b1l}
// p0 = Wsi (wide 64x256), p1 = Ws2 (narrow 256x64), p2 = Wmh, p3 = Wm2
__device__ uint4  g_Wpk[4*4096];

// ================= helpers =================
__device__ __forceinline__ float ftanh(float x) {
    float ax = fabsf(x);
    float e  = __expf(-2.f*ax);
    float t  = __fdividef(1.f - e, 1.f + e);
    return copysignf(t, x);
}
__device__ __forceinline__ float fsigmoid(float x) {
    return __fdividef(1.f, 1.f + __expf(-x));
}
__device__ __forceinline__ u64 pack2(float x) {
    u64 r; unsigned xi = __float_as_uint(x);
    asm("mov.b64 %0, {%1,%1};" : "=l"(r) : "r"(xi));
    return r;
}
__device__ __forceinline__ float2 unpack2(u64 v) {
    unsigned lo, hi;
    asm("mov.b64 {%0,%1}, %2;" : "=r"(lo), "=r"(hi) : "l"(v));
    return make_float2(__uint_as_float(lo), __uint_as_float(hi));
}
__device__ __forceinline__ void ffma2(u64& d, u64 a, u64 b) {
    asm("fma.rn.f32x2 %0, %1, %2, %0;" : "+l"(d) : "l"(a), "l"(b));
}
// split (a,b) into bf16 hi-pair and lo-pair; lower 16 bits = a
__device__ __forceinline__ void split2(float a, float b, uint32_t& hi, uint32_t& lo) {
    uint32_t h;
    asm("cvt.rn.bf16x2.f32 %0, %1, %2;" : "=r"(h) : "f"(b), "f"(a));
    float ra = a - __uint_as_float(h << 16);
    float rb = b - __uint_as_float(h & 0xffff0000u);
    uint32_t l;
    asm("cvt.rn.bf16x2.f32 %0, %1, %2;" : "=r"(l) : "f"(rb), "f"(ra));
    hi = h; lo = l;
}
__device__ __forceinline__ void ldm_x4(uint32_t* r, uint32_t addr) {
    asm volatile("ldmatrix.sync.aligned.m8n8.x4.shared.b16 {%0,%1,%2,%3}, [%4];"
        : "=r"(r[0]), "=r"(r[1]), "=r"(r[2]), "=r"(r[3]) : "r"(addr));
}
__device__ __forceinline__ void mma_bf16(float* d, const uint32_t* a,
                                         uint32_t b0, uint32_t b1) {
    asm volatile("mma.sync.aligned.m16n8k16.row.col.f32.bf16.bf16.f32 "
        "{%0,%1,%2,%3}, {%4,%5,%6,%7}, {%8,%9}, {%0,%1,%2,%3};"
        : "+f"(d[0]), "+f"(d[1]), "+f"(d[2]), "+f"(d[3])
        : "r"(a[0]), "r"(a[1]), "r"(a[2]), "r"(a[3]), "r"(b0), "r"(b1));
}
__device__ __forceinline__ uint32_t smem_u32(const void* p) {
    uint32_t a;
    asm("{ .reg .u64 t; cvta.to.shared.u64 t, %1; cvt.u32.u64 %0, t; }"
        : "=r"(a) : "l"(p));
    return a;
}

// ================= init: copy state, build const-W, pack mma weights =================
__global__ void k_init(const float* __restrict__ h_in, const float* __restrict__ msg_in,
                       const float* __restrict__ sw1, const float* __restrict__ sw2,
                       const float* __restrict__ mw1, const float* __restrict__ mw2)
{
    int i0 = blockIdx.x*blockDim.x + threadIdx.x;
    int stride = gridDim.x*blockDim.x;
    float* gh  = (float*)g_h2;
    float* gm0 = (float*)g_msg2[0];
    for (int i = i0; i < ROWS*DD; i += stride) { gh[i] = h_in[i]; gm0[i] = msg_in[i]; }
    for (int i = i0; i < 129*HSZ; i += stride) {
        int j = i >> 8, h = i & 255;
        g_WsC[i] = (j < 128) ? sw1[h*193 + 64 + j] : sw1[h*193 + 192];
        g_WmC[i] = (j < 128) ? mw1[h*192 + 64 + j] : 0.f;
    }
    for (int e = i0; e < 4*4096; e += stride) {
        int p = e >> 12, r = e & 4095;
        int lane = r & 31, q = r >> 5;
        int NT = (p == 0 || p == 2) ? 32 : 8;
        int kt = q / NT, nt = q - kt*NT;
        int k0 = kt*16 + (lane & 3)*2;
        int n  = nt*8 + (lane >> 2);
        float w00, w01, w10, w11;
        if (p == 0)      { const float* s = sw1 + (size_t)n*193;
                           w00 = s[k0]; w01 = s[k0+1]; w10 = s[k0+8]; w11 = s[k0+9]; }
        else if (p == 1) { const float* s = sw2 + (size_t)n*256;
                           w00 = s[k0]; w01 = s[k0+1]; w10 = s[k0+8]; w11 = s[k0+9]; }
        else if (p == 2) { const float* s = mw1 + (size_t)n*192;
                           w00 = s[k0]; w01 = s[k0+1]; w10 = s[k0+8]; w11 = s[k0+9]; }
        else             { const float* s = mw2 + (size_t)n*256;
                           w00 = s[k0]; w01 = s[k0+1]; w10 = s[k0+8]; w11 = s[k0+9]; }
        uint32_t b0h, b0l, b1h, b1l;
        split2(w00, w01, b0h, b0l);
        split2(w10, w11, b1h, b1l);
        g_Wpk[e] = make_uint4(b0h, b1h, b0l, b1l);
    }
}

// ================= per-neuron modulation MLP (unchanged) =================
__global__ void k_mod(const float* __restrict__ h_in, const float* __restrict__ heb,
                      const float* __restrict__ dec_in, const float* __restrict__ prim_in,
                      const float* __restrict__ wconn_in,
                      const float* __restrict__ mw1, const float* __restrict__ mb1,
                      const float* __restrict__ mw2, const float* __restrict__ mb2,
                      const float* __restrict__ nid)
{
    const int n = blockIdx.x;
    const int tid = threadIdx.x;
    const int warp = tid >> 5, lane = tid & 31;
    __shared__ float xs[BSZ*225];
    __shared__ float hid[BSZ*64];
    __shared__ float dlt[BSZ*97];

    for (int i = tid; i < BSZ*225; i += 256) {
        int b = i / 225, j = i - b*225;
        size_t bn = (size_t)b*NN + n;
        float v;
        if (j < 32)        v = heb[bn*32 + j];
        else if (j < 96)   v = h_in[bn*64 + (j-32)];
        else if (j == 96)  v = dec_in[bn];
        else if (j < 161)  v = prim_in[bn*64 + (j-97)];
        else               v = nid[(size_t)n*64 + (j-161)];
        xs[i] = v;
    }
    __syncthreads();

    const float* w1 = mw1 + (size_t)n*64*225;
    for (int hh = warp; hh < 64; hh += 8) {
        float acc[BSZ];
        #pragma unroll
        for (int b = 0; b < BSZ; b++) acc[b] = 0.f;
        for (int j = lane; j < 225; j += 32) {
            float w = w1[hh*225 + j];
            #pragma unroll
            for (int b = 0; b < BSZ; b++) acc[b] += w * xs[b*225 + j];
        }
        #pragma unroll
        for (int off = 16; off; off >>= 1) {
            #pragma unroll
            for (int b = 0; b < BSZ; b++) acc[b] += __shfl_xor_sync(0xffffffffu, acc[b], off);
        }
        if (lane == 0) {
            float bb = mb1[(size_t)n*64 + hh];
            #pragma unroll
            for (int b = 0; b < BSZ; b++) hid[b*64 + hh] = ftanh(acc[b] + bb);
        }
    }
    __syncthreads();

    const float* w2 = mw2 + (size_t)n*64*97;
    for (int o = warp; o < 97; o += 8) {
        float acc[BSZ];
        #pragma unroll
        for (int b = 0; b < BSZ; b++) acc[b] = 0.f;
        #pragma unroll
        for (int j2 = 0; j2 < 2; ++j2) {
            int j = lane + 32*j2;
            float w = w2[(size_t)j*97 + o];
            #pragma unroll
            for (int b = 0; b < BSZ; b++) acc[b] += w * hid[b*64 + j];
        }
        #pragma unroll
        for (int off = 16; off; off >>= 1) {
            #pragma unroll
            for (int b = 0; b < BSZ; b++) acc[b] += __shfl_xor_sync(0xffffffffu, acc[b], off);
        }
        if (lane == 0) {
            float bb = mb2[(size_t)n*97 + o];
            #pragma unroll
            for (int b = 0; b < BSZ; b++) dlt[b*97 + o] = acc[b] + bb;
        }
    }
    __syncthreads();

    float* wsig = (float*)g_wsig4;
    for (int i = tid; i < BSZ*KK; i += 256) {
        int b = i >> 5, k = i & 31;
        size_t bn = (size_t)b*NN + n;
        wsig[bn*32 + k] = fsigmoid(wconn_in[bn*32 + k] + dlt[b*97 + k]);
    }
    if (tid < BSZ) {
        size_t bn = (size_t)tid*NN + n;
        float v = dec_in[bn] + dlt[tid*97 + 32];
        g_dec[bn] = v;
        g_d[bn] = fsigmoid(v);
    }
    if (warp < BSZ) {
        int b = warp;
        size_t bn = (size_t)b*NN + n;
        float p0 = prim_in[bn*64 + lane]      + dlt[b*97 + 33 + lane];
        float p1 = prim_in[bn*64 + lane + 32] + dlt[b*97 + 33 + lane + 32];
        float ss = p0*p0 + p1*p1;
        #pragma unroll
        for (int off = 16; off; off >>= 1) ss += __shfl_xor_sync(0xffffffffu, ss, off);
        float sc = rsqrtf(ss*(1.f/64.f) + 1e-6f);
        g_prim[bn*64 + lane]      = p0*sc;
        g_prim[bn*64 + lane + 32] = p1*sc;
    }
}

// ================= state_const / msg_const (unchanged) =================
__global__ __launch_bounds__(256, 4)
void k_const(const float* __restrict__ sb1, const float* __restrict__ mb1_,
             const float* __restrict__ nid)
{
    __shared__ float xs[64*132];
    const int tid = threadIdx.x;
    const int r0 = blockIdx.x * 64;
    const int which = blockIdx.y;
    const float* WC = which ? g_WsC : g_WmC;
    const float* b1 = which ? sb1 : mb1_;
    float* outp     = which ? g_sconst : g_mconst;

    for (int i = tid; i < 64*132; i += 256) {
        int rr = i / 132, j = i - rr*132;
        size_t r = (size_t)(r0 + rr);
        int nn_ = (int)(r & (NN-1));
        float v = 0.f;
        if (j < 64)        v = g_prim[r*64 + j];
        else if (j < 128)  v = nid[(size_t)nn_*64 + (j-64)];
        else if (j == 128) v = g_dec[r];
        xs[i] = v;
    }
    __syncthreads();

    const int ty = tid >> 5, tx = tid & 31;
    float acc[8][8];
    #pragma unroll
    for (int i = 0; i < 8; i++)
        #pragma unroll
        for (int u = 0; u < 8; u++) acc[i][u] = 0.f;
    for (int j = 0; j < 129; ++j) {
        float a[8], w[8];
        #pragma unroll
        for (int i = 0; i < 8; i++) a[i] = xs[(ty*8+i)*132 + j];
        #pragma unroll
        for (int u = 0; u < 8; u++) w[u] = __ldg(WC + j*256 + tx + 32*u);
        #pragma unroll
        for (int i = 0; i < 8; i++)
            #pragma unroll
            for (int u = 0; u < 8; u++) acc[i][u] += a[i]*w[u];
    }
    #pragma unroll
    for (int i = 0; i < 8; i++) {
        int r = r0 + ty*8 + i;
        #pragma unroll
        for (int u = 0; u < 8; u++) {
            int c = tx + 32*u;
            outp[(size_t)r*256 + c] = acc[i][u] + __ldg(b1 + c);
        }
    }
}

// ================= pipelined fused wide->tanh->narrow (registers only) =================
// wide_mma: issue 24 HMMAs for chunk kt into split accumulators + prefetch const
__device__ __forceinline__ void wide_mma(
    const uint32_t A0[4][4], const uint32_t A1[4][4],
    const uint4* __restrict__ Wwide, const float* __restrict__ cst,
    int kt, int ln, int gr, int q, float d[2][2][4], float2 cc_[2][2])
{
    #pragma unroll
    for (int half = 0; half < 2; ++half) {
        const int nt = 2*kt + half;
        #pragma unroll
        for (int s = 0; s < 2; ++s)
            #pragma unroll
            for (int i = 0; i < 4; ++i) d[half][s][i] = 0.f;
        #pragma unroll
        for (int wk = 0; wk < 4; ++wk) {
            uint4 u = __ldg(Wwide + (size_t)(wk*32 + nt)*32 + ln);
            mma_bf16(d[half][0], A0[wk], u.x, u.y);   // chain depth 4
            mma_bf16(d[half][1], A0[wk], u.z, u.w);   // chain depth 8
            mma_bf16(d[half][1], A1[wk], u.x, u.y);
        }
        const int c0 = nt*8 + q*2;
        cc_[half][0] = *(const float2*)(cst + (size_t)gr*256 + c0);
        cc_[half][1] = *(const float2*)(cst + (size_t)(gr+8)*256 + c0);
    }
}

// wide_epi: tanh + bf16 split -> narrow A-fragment registers
__device__ __forceinline__ void wide_epi(const float d[2][2][4], const float2 cc_[2][2],
                                         uint32_t ah[4], uint32_t al[4])
{
    #pragma unroll
    for (int half = 0; half < 2; ++half) {
        float h0 = ftanh(d[half][0][0] + d[half][1][0] + cc_[half][0].x);
        float h1 = ftanh(d[half][0][1] + d[half][1][1] + cc_[half][0].y);
        float h2 = ftanh(d[half][0][2] + d[half][1][2] + cc_[half][1].x);
        float h3 = ftanh(d[half][0][3] + d[half][1][3] + cc_[half][1].y);
        split2(h0, h1, ah[half*2],   al[half*2]);
        split2(h2, h3, ah[half*2+1], al[half*2+1]);
    }
}

// narrow_step: 24 HMMAs for hid chunk kt (8 independent n-tile chains)
__device__ __forceinline__ void narrow_step(const uint32_t ah[4], const uint32_t al[4],
                                            const uint4* __restrict__ Wn, int kt, int ln,
                                            float nacc[8][4])
{
    #pragma unroll
    for (int nt = 0; nt < 8; ++nt) {
        uint4 u = __ldg(Wn + (size_t)(kt*8 + nt)*32 + ln);
        mma_bf16(nacc[nt], ah, u.x, u.y);
        mma_bf16(nacc[nt], ah, u.z, u.w);
        mma_bf16(nacc[nt], al, u.x, u.y);
    }
}

__device__ __forceinline__ void fused_wide_narrow(
    const uint32_t Ah[4][4], const uint32_t Al[4][4],
    const uint4* __restrict__ Wwide, const uint4* __restrict__ Wnarrow,
    const float* __restrict__ cst, int ln, float nacc[8][4])
{
    const int gr = ln >> 2, q = ln & 3;
    #pragma unroll
    for (int nt = 0; nt < 8; nt++)
        #pragma unroll
        for (int i = 0; i < 4; i++) nacc[nt][i] = 0.f;

    float d[2][2][4]; float2 cc_[2][2];
    uint32_t ah[4], al[4];
    wide_mma(Ah, Al, Wwide, cst, 0, ln, gr, q, d, cc_);
    wide_epi(d, cc_, ah, al);
    #pragma unroll 1
    for (int kt = 1; kt < 16; ++kt) {
        float d2[2][2][4]; float2 cc2[2][2];
        wide_mma(Ah, Al, Wwide, cst, kt, ln, gr, q, d2, cc2);  // fills pipe
        narrow_step(ah, al, Wnarrow, kt-1, ln, nacc);          // overlaps wide latency
        wide_epi(d2, cc2, ah, al);
    }
    narrow_step(ah, al, Wnarrow, 15, ln, nacc);
}

// ================= fused step: gather -> (wide+narrow)x2, register-chained =================
#define A_STRIDE   144
#define AH_OFF     0
#define AL_OFF     2304
#define WARP_BYTES 4608
#define STEP_SMEM  (4*WARP_BYTES)

__global__ __launch_bounds__(128, 3)
void k_step(int t, const float* __restrict__ cc, const int* __restrict__ conn,
            const float* __restrict__ nid, const float* __restrict__ sb2,
            const float* __restrict__ mb2, float* __restrict__ out)
{
    extern __shared__ char smem[];
    const int tid = threadIdx.x;
    const int w   = tid >> 5, ln = tid & 31;
    char*    wmem = smem + w*WARP_BYTES;
    const uint32_t wsm = smem_u32(smem) + w*WARP_BYTES;

    const int b      = blockIdx.y;
    const int ntblk  = blockIdx.x;
    const int n0     = ntblk*64;
    const int nfirst = n0 + w*16;
    const int sel    = t & 1;
    const size_t growbase = (size_t)b*NN + nfirst;

    // ---- phase 0: gather (+inject) -> bf16 h/l A-tile in smem ----
    {
        const u64*    mq  = (const u64*)g_msg2[sel] + (size_t)b*NN*32;
        const int4*   cn4 = (const int4*)conn;
        const float4* ws4 = (const float4*)g_wsig4;
        #pragma unroll 1
        for (int g = 0; g < 16; ++g) {
            const int n = nfirst + g;
            const size_t cb = (size_t)n*8;
            const size_t wb = ((size_t)b*NN + n)*8;
            u64 a0 = 0ull, a1 = 0ull;
            #pragma unroll
            for (int kq = 0; kq < 8; ++kq) {
                int4   id = __ldg(cn4 + cb + kq);
                float4 wt = __ldg(ws4 + wb + kq);
                ffma2(a0, pack2(wt.x), mq[(size_t)id.x*32 + ln]);
                ffma2(a1, pack2(wt.y), mq[(size_t)id.y*32 + ln]);
                ffma2(a0, pack2(wt.z), mq[(size_t)id.z*32 + ln]);
                ffma2(a1, pack2(wt.w), mq[(size_t)id.w*32 + ln]);
            }
            float2 v0 = unpack2(a0), v1 = unpack2(a1);
            float x0 = v0.x + v1.x, x1 = v0.y + v1.y;
            if ((n & 127) < 4) {
                float2 cv = *(const float2*)(cc + ((size_t)b*TT + t)*2048 + (n>>7)*64 + ln*2);
                x0 += cv.x; x1 += cv.y;
            }
            uint32_t hi, lo;
            split2(x0, x1, hi, lo);
            *(uint32_t*)(wmem + AH_OFF + g*A_STRIDE + ln*4) = hi;
            *(uint32_t*)(wmem + AL_OFF + g*A_STRIDE + ln*4) = lo;
        }
    }
    __syncwarp();

    // load gather A-frags once; smem A region free afterwards
    uint32_t Ah[4][4], Al[4][4];
    {
        const int row = ln & 15;
        const uint32_t coff = (uint32_t)((ln >> 4) << 4);
        #pragma unroll
        for (int kt = 0; kt < 4; kt++) {
            uint32_t ad = wsm + AH_OFF + row*A_STRIDE + kt*32 + coff;
            ldm_x4(Ah[kt], ad);
            ldm_x4(Al[kt], ad + (AL_OFF - AH_OFF));
        }
    }
    __syncwarp();

    const int gr = ln >> 2, q = ln & 3;
    float nacc[8][4];

    // ---- phases 1+2: hid = tanh(recv@Wsi + sconst); nacc = hid@Ws2 ----
    fused_wide_narrow(Ah, Al, g_Wpk, g_Wpk + 4096,
                      g_sconst + growbase*256, ln, nacc);

    // ---- phase 2 epilogue: h update; build phase-3 A-frags in regs ----
    uint32_t Hh[4][4], Hl[4][4];
    {
        const float dv0 = g_d[growbase + gr];
        const float dv1 = g_d[growbase + gr + 8];
        // batch the h loads first (independent LDGs, MLP-overlapped)
        float2 ho0[8], ho1[8];
        #pragma unroll
        for (int nt = 0; nt < 8; ++nt) {
            const int ci = (nt*8 + q*2) >> 1;
            ho0[nt] = g_h2[(growbase + gr)*32 + ci];
            ho1[nt] = g_h2[(growbase + gr + 8)*32 + ci];
        }
        #pragma unroll
        for (int nt = 0; nt < 8; ++nt) {
            const int c0 = nt*8 + q*2;
            float2 bb = *(const float2*)(sb2 + c0);
            // row gr
            {
                float u0 = ftanh(nacc[nt][0] + bb.x), u1 = ftanh(nacc[nt][1] + bb.y);
                float hv0 = dv0*ho0[nt].x + (1.f-dv0)*u0, hv1 = dv0*ho0[nt].y + (1.f-dv0)*u1;
                g_h2[(growbase + gr)*32 + (c0 >> 1)] = make_float2(hv0, hv1);
                split2(hv0, hv1, Hh[nt>>1][(nt&1)*2], Hl[nt>>1][(nt&1)*2]);
            }
            // row gr+8
            {
                float u0 = ftanh(nacc[nt][2] + bb.x), u1 = ftanh(nacc[nt][3] + bb.y);
                float hv0 = dv1*ho1[nt].x + (1.f-dv1)*u0, hv1 = dv1*ho1[nt].y + (1.f-dv1)*u1;
                g_h2[(growbase + gr + 8)*32 + (c0 >> 1)] = make_float2(hv0, hv1);
                split2(hv0, hv1, Hh[nt>>1][(nt&1)*2+1], Hl[nt>>1][(nt&1)*2+1]);
            }
        }
    }

    // ---- phases 3+4: mh = tanh(h@Wmh + mconst); nacc = mh@Wm2 ----
    fused_wide_narrow(Hh, Hl, g_Wpk + 2*4096, g_Wpk + 3*4096,
                      g_mconst + growbase*256, ln, nacc);

    // ---- phase 4 epilogue: msg = tanh(.+mb2)+nid; readout ----
    {
        const int roflag = (ntblk & 1) && (w == 3);
        float2* msgout = g_msg2[sel ^ 1];
        float* s_ro = (float*)wmem;      // gather A region, free now
        #pragma unroll
        for (int nt = 0; nt < 8; ++nt) {
            const int c0 = nt*8 + q*2;
            float2 bb = *(const float2*)(mb2 + c0);
            // row gr
            {
                int n = nfirst + gr;
                size_t grow = growbase + gr;
                float2 nv = *(const float2*)(nid + (size_t)n*64 + c0);
                float m0 = ftanh(nacc[nt][0] + bb.x) + nv.x;
                float m1 = ftanh(nacc[nt][1] + bb.y) + nv.y;
                msgout[grow*32 + (c0 >> 1)] = make_float2(m0, m1);
            }
            // row gr+8
            {
                int n = nfirst + gr + 8;
                size_t grow = growbase + gr + 8;
                float2 nv = *(const float2*)(nid + (size_t)n*64 + c0);
                float m0 = ftanh(nacc[nt][2] + bb.x) + nv.x;
                float m1 = ftanh(nacc[nt][3] + bb.y) + nv.y;
                msgout[grow*32 + (c0 >> 1)] = make_float2(m0, m1);
                if (roflag && gr >= 4)
                    *(float2*)(s_ro + (gr-4)*64 + c0) = make_float2(m0, m1);
            }
        }
        __syncwarp();
        if (roflag) {
            size_t obase = ((size_t)b*TT + t)*2048 + (ntblk >> 1)*64;
            float v0 = 0.25f*(s_ro[ln]      + s_ro[64+ln]  + s_ro[128+ln] + s_ro[192+ln]);
            float v1 = 0.25f*(s_ro[32+ln]   + s_ro[96+ln]  + s_ro[160+ln] + s_ro[224+ln]);
            out[obase + ln]      = v0;
            out[obase + 32 + ln] = v1;
        }
    }
}

// ================= launcher =================
extern "C" void kernel_launch(void* const* d_in, const int* in_sizes, int n_in,
                              void* d_out, int out_size)
{
    const float* cc      = (const float*)d_in[0];
    const float* h_in    = (const float*)d_in[1];
    const float* msg_in  = (const float*)d_in[2];
    const float* wconn   = (const float*)d_in[3];
    const float* declog  = (const float*)d_in[4];
    const float* prim_in = (const float*)d_in[5];
    const float* heb     = (const float*)d_in[6];
    const float* sw1     = (const float*)d_in[7];
    const float* sb1     = (const float*)d_in[8];
    const float* sw2     = (const float*)d_in[9];
    const float* sb2     = (const float*)d_in[10];
    const float* mw1     = (const float*)d_in[11];
    const float* mb1     = (const float*)d_in[12];
    const float* mw2     = (const float*)d_in[13];
    const float* mb2     = (const float*)d_in[14];
    const float* modw1   = (const float*)d_in[15];
    const float* modb1   = (const float*)d_in[16];
    const float* modw2   = (const float*)d_in[17];
    const float* modb2   = (const float*)d_in[18];
    const float* nid     = (const float*)d_in[19];
    const int*   conn    = (const int*)d_in[20];
    float* out = (float*)d_out;

    cudaFuncSetAttribute(k_step, cudaFuncAttributeMaxDynamicSharedMemorySize, STEP_SMEM);

    k_init<<<256, 256>>>(h_in, msg_in, sw1, sw2, mw1, mw2);
    k_mod<<<NN, 256>>>(h_in, heb, declog, prim_in, wconn,
                       modw1, modb1, modw2, modb2, nid);
    k_const<<<dim3(512, 2), 256>>>(sb1, mb1, nid);

    for (int t = 0; t < TT; ++t) {
        k_step<<<dim3(NN/64, BSZ), 128, STEP_SMEM>>>(t, cc, conn, nid, sb2, mb2, out);
    }
}

// round 13
// speedup vs baseline: 1.6653x; 1.1417x over previous
#include <cuda_runtime.h>
#include <math.h>
#include <stdint.h>

#define NN   4096
#define KK   32
#define DD   64
#define BSZ  8
#define TT   32
#define HSZ  256
#define ROWS (BSZ*NN)

typedef unsigned long long u64;

// ================= persistent device scratch =================
__device__ float4 g_wsig4[ROWS*KK/4];
__device__ float  g_d[ROWS];
__device__ float  g_dec[ROWS];
__device__ float  g_prim[ROWS*DD];
__device__ float  g_sconst[(size_t)ROWS*HSZ];   // [row][256]
__device__ float  g_mconst[(size_t)ROWS*HSZ];
__device__ float2 g_h2[ROWS*DD/2];              // [row][32 float2]
__device__ float2 g_msg2[2][ROWS*DD/2];
__device__ float  g_WsC[129*HSZ];               // const-GEMM weights [j][h]
__device__ float  g_WmC[129*HSZ];
// fragment-packed bf16 weights: phase p*4096 .. : uint4 = {b0h,b1h,b0l,b1l}
// p0 = Wsi (wide 64x256), p1 = Ws2 (narrow 256x64), p2 = Wmh, p3 = Wm2
__device__ uint4  g_Wpk[4*4096];

// ================= helpers =================
__device__ __forceinline__ float ftanh(float x) {
    float ax = fabsf(x);
    float e  = __expf(-2.f*ax);
    float t  = __fdividef(1.f - e, 1.f + e);
    return copysignf(t, x);
}
__device__ __forceinline__ float fsigmoid(float x) {
    return __fdividef(1.f, 1.f + __expf(-x));
}
__device__ __forceinline__ u64 pack2(float x) {
    u64 r; unsigned xi = __float_as_uint(x);
    asm("mov.b64 %0, {%1,%1};" : "=l"(r) : "r"(xi));
    return r;
}
__device__ __forceinline__ float2 unpack2(u64 v) {
    unsigned lo, hi;
    asm("mov.b64 {%0,%1}, %2;" : "=r"(lo), "=r"(hi) : "l"(v));
    return make_float2(__uint_as_float(lo), __uint_as_float(hi));
}
__device__ __forceinline__ void ffma2(u64& d, u64 a, u64 b) {
    asm("fma.rn.f32x2 %0, %1, %2, %0;" : "+l"(d) : "l"(a), "l"(b));
}
// split (a,b) into bf16 hi-pair and lo-pair; lower 16 bits = a
__device__ __forceinline__ void split2(float a, float b, uint32_t& hi, uint32_t& lo) {
    uint32_t h;
    asm("cvt.rn.bf16x2.f32 %0, %1, %2;" : "=r"(h) : "f"(b), "f"(a));
    float ra = a - __uint_as_float(h << 16);
    float rb = b - __uint_as_float(h & 0xffff0000u);
    uint32_t l;
    asm("cvt.rn.bf16x2.f32 %0, %1, %2;" : "=r"(l) : "f"(rb), "f"(ra));
    hi = h; lo = l;
}
__device__ __forceinline__ void ldm_x4(uint32_t* r, uint32_t addr) {
    asm volatile("ldmatrix.sync.aligned.m8n8.x4.shared.b16 {%0,%1,%2,%3}, [%4];"
        : "=r"(r[0]), "=r"(r[1]), "=r"(r[2]), "=r"(r[3]) : "r"(addr));
}
__device__ __forceinline__ void mma_bf16(float* d, const uint32_t* a,
                                         uint32_t b0, uint32_t b1) {
    asm volatile("mma.sync.aligned.m16n8k16.row.col.f32.bf16.bf16.f32 "
        "{%0,%1,%2,%3}, {%4,%5,%6,%7}, {%8,%9}, {%0,%1,%2,%3};"
        : "+f"(d[0]), "+f"(d[1]), "+f"(d[2]), "+f"(d[3])
        : "r"(a[0]), "r"(a[1]), "r"(a[2]), "r"(a[3]), "r"(b0), "r"(b1));
}
__device__ __forceinline__ uint32_t smem_u32(const void* p) {
    uint32_t a;
    asm("{ .reg .u64 t; cvta.to.shared.u64 t, %1; cvt.u32.u64 %0, t; }"
        : "=r"(a) : "l"(p));
    return a;
}

// ================= init: copy state, build const-W, pack mma weights =================
__global__ void k_init(const float* __restrict__ h_in, const float* __restrict__ msg_in,
                       const float* __restrict__ sw1, const float* __restrict__ sw2,
                       const float* __restrict__ mw1, const float* __restrict__ mw2)
{
    int i0 = blockIdx.x*blockDim.x + threadIdx.x;
    int stride = gridDim.x*blockDim.x;
    float* gh  = (float*)g_h2;
    float* gm0 = (float*)g_msg2[0];
    for (int i = i0; i < ROWS*DD; i += stride) { gh[i] = h_in[i]; gm0[i] = msg_in[i]; }
    for (int i = i0; i < 129*HSZ; i += stride) {
        int j = i >> 8, h = i & 255;
        g_WsC[i] = (j < 128) ? sw1[h*193 + 64 + j] : sw1[h*193 + 192];
        g_WmC[i] = (j < 128) ? mw1[h*192 + 64 + j] : 0.f;
    }
    for (int e = i0; e < 4*4096; e += stride) {
        int p = e >> 12, r = e & 4095;
        int lane = r & 31, q = r >> 5;
        int NT = (p == 0 || p == 2) ? 32 : 8;
        int kt = q / NT, nt = q - kt*NT;
        int k0 = kt*16 + (lane & 3)*2;
        int n  = nt*8 + (lane >> 2);
        float w00, w01, w10, w11;
        if (p == 0)      { const float* s = sw1 + (size_t)n*193;
                           w00 = s[k0]; w01 = s[k0+1]; w10 = s[k0+8]; w11 = s[k0+9]; }
        else if (p == 1) { const float* s = sw2 + (size_t)n*256;
                           w00 = s[k0]; w01 = s[k0+1]; w10 = s[k0+8]; w11 = s[k0+9]; }
        else if (p == 2) { const float* s = mw1 + (size_t)n*192;
                           w00 = s[k0]; w01 = s[k0+1]; w10 = s[k0+8]; w11 = s[k0+9]; }
        else             { const float* s = mw2 + (size_t)n*256;
                           w00 = s[k0]; w01 = s[k0+1]; w10 = s[k0+8]; w11 = s[k0+9]; }
        uint32_t b0h, b0l, b1h, b1l;
        split2(w00, w01, b0h, b0l);
        split2(w10, w11, b1h, b1l);
        g_Wpk[e] = make_uint4(b0h, b1h, b0l, b1l);
    }
}

// ================= per-neuron modulation MLP (unchanged) =================
__global__ void k_mod(const float* __restrict__ h_in, const float* __restrict__ heb,
                      const float* __restrict__ dec_in, const float* __restrict__ prim_in,
                      const float* __restrict__ wconn_in,
                      const float* __restrict__ mw1, const float* __restrict__ mb1,
                      const float* __restrict__ mw2, const float* __restrict__ mb2,
                      const float* __restrict__ nid)
{
    const int n = blockIdx.x;
    const int tid = threadIdx.x;
    const int warp = tid >> 5, lane = tid & 31;
    __shared__ float xs[BSZ*225];
    __shared__ float hid[BSZ*64];
    __shared__ float dlt[BSZ*97];

    for (int i = tid; i < BSZ*225; i += 256) {
        int b = i / 225, j = i - b*225;
        size_t bn = (size_t)b*NN + n;
        float v;
        if (j < 32)        v = heb[bn*32 + j];
        else if (j < 96)   v = h_in[bn*64 + (j-32)];
        else if (j == 96)  v = dec_in[bn];
        else if (j < 161)  v = prim_in[bn*64 + (j-97)];
        else               v = nid[(size_t)n*64 + (j-161)];
        xs[i] = v;
    }
    __syncthreads();

    const float* w1 = mw1 + (size_t)n*64*225;
    for (int hh = warp; hh < 64; hh += 8) {
        float acc[BSZ];
        #pragma unroll
        for (int b = 0; b < BSZ; b++) acc[b] = 0.f;
        for (int j = lane; j < 225; j += 32) {
            float w = w1[hh*225 + j];
            #pragma unroll
            for (int b = 0; b < BSZ; b++) acc[b] += w * xs[b*225 + j];
        }
        #pragma unroll
        for (int off = 16; off; off >>= 1) {
            #pragma unroll
            for (int b = 0; b < BSZ; b++) acc[b] += __shfl_xor_sync(0xffffffffu, acc[b], off);
        }
        if (lane == 0) {
            float bb = mb1[(size_t)n*64 + hh];
            #pragma unroll
            for (int b = 0; b < BSZ; b++) hid[b*64 + hh] = ftanh(acc[b] + bb);
        }
    }
    __syncthreads();

    const float* w2 = mw2 + (size_t)n*64*97;
    for (int o = warp; o < 97; o += 8) {
        float acc[BSZ];
        #pragma unroll
        for (int b = 0; b < BSZ; b++) acc[b] = 0.f;
        #pragma unroll
        for (int j2 = 0; j2 < 2; ++j2) {
            int j = lane + 32*j2;
            float w = w2[(size_t)j*97 + o];
            #pragma unroll
            for (int b = 0; b < BSZ; b++) acc[b] += w * hid[b*64 + j];
        }
        #pragma unroll
        for (int off = 16; off; off >>= 1) {
            #pragma unroll
            for (int b = 0; b < BSZ; b++) acc[b] += __shfl_xor_sync(0xffffffffu, acc[b], off);
        }
        if (lane == 0) {
            float bb = mb2[(size_t)n*97 + o];
            #pragma unroll
            for (int b = 0; b < BSZ; b++) dlt[b*97 + o] = acc[b] + bb;
        }
    }
    __syncthreads();

    float* wsig = (float*)g_wsig4;
    for (int i = tid; i < BSZ*KK; i += 256) {
        int b = i >> 5, k = i & 31;
        size_t bn = (size_t)b*NN + n;
        wsig[bn*32 + k] = fsigmoid(wconn_in[bn*32 + k] + dlt[b*97 + k]);
    }
    if (tid < BSZ) {
        size_t bn = (size_t)tid*NN + n;
        float v = dec_in[bn] + dlt[tid*97 + 32];
        g_dec[bn] = v;
        g_d[bn] = fsigmoid(v);
    }
    if (warp < BSZ) {
        int b = warp;
        size_t bn = (size_t)b*NN + n;
        float p0 = prim_in[bn*64 + lane]      + dlt[b*97 + 33 + lane];
        float p1 = prim_in[bn*64 + lane + 32] + dlt[b*97 + 33 + lane + 32];
        float ss = p0*p0 + p1*p1;
        #pragma unroll
        for (int off = 16; off; off >>= 1) ss += __shfl_xor_sync(0xffffffffu, ss, off);
        float sc = rsqrtf(ss*(1.f/64.f) + 1e-6f);
        g_prim[bn*64 + lane]      = p0*sc;
        g_prim[bn*64 + lane + 32] = p1*sc;
    }
}

// ================= state_const / msg_const (unchanged) =================
__global__ __launch_bounds__(256, 4)
void k_const(const float* __restrict__ sb1, const float* __restrict__ mb1_,
             const float* __restrict__ nid)
{
    __shared__ float xs[64*132];
    const int tid = threadIdx.x;
    const int r0 = blockIdx.x * 64;
    const int which = blockIdx.y;
    const float* WC = which ? g_WsC : g_WmC;
    const float* b1 = which ? sb1 : mb1_;
    float* outp     = which ? g_sconst : g_mconst;

    for (int i = tid; i < 64*132; i += 256) {
        int rr = i / 132, j = i - rr*132;
        size_t r = (size_t)(r0 + rr);
        int nn_ = (int)(r & (NN-1));
        float v = 0.f;
        if (j < 64)        v = g_prim[r*64 + j];
        else if (j < 128)  v = nid[(size_t)nn_*64 + (j-64)];
        else if (j == 128) v = g_dec[r];
        xs[i] = v;
    }
    __syncthreads();

    const int ty = tid >> 5, tx = tid & 31;
    float acc[8][8];
    #pragma unroll
    for (int i = 0; i < 8; i++)
        #pragma unroll
        for (int u = 0; u < 8; u++) acc[i][u] = 0.f;
    for (int j = 0; j < 129; ++j) {
        float a[8], w[8];
        #pragma unroll
        for (int i = 0; i < 8; i++) a[i] = xs[(ty*8+i)*132 + j];
        #pragma unroll
        for (int u = 0; u < 8; u++) w[u] = __ldg(WC + j*256 + tx + 32*u);
        #pragma unroll
        for (int i = 0; i < 8; i++)
            #pragma unroll
            for (int u = 0; u < 8; u++) acc[i][u] += a[i]*w[u];
    }
    #pragma unroll
    for (int i = 0; i < 8; i++) {
        int r = r0 + ty*8 + i;
        #pragma unroll
        for (int u = 0; u < 8; u++) {
            int c = tx + 32*u;
            outp[(size_t)r*256 + c] = acc[i][u] + __ldg(b1 + c);
        }
    }
}

// ================= pipelined fused wide->tanh->narrow (registers only) =================
__device__ __forceinline__ void wide_mma(
    const uint32_t A0[4][4], const uint32_t A1[4][4],
    const uint4* __restrict__ Wwide, const float* __restrict__ cst,
    int kt, int ln, int gr, int q, float d[2][2][4], float2 cc_[2][2])
{
    #pragma unroll
    for (int half = 0; half < 2; ++half) {
        const int nt = 2*kt + half;
        #pragma unroll
        for (int s = 0; s < 2; ++s)
            #pragma unroll
            for (int i = 0; i < 4; ++i) d[half][s][i] = 0.f;
        #pragma unroll
        for (int wk = 0; wk < 4; ++wk) {
            uint4 u = __ldg(Wwide + (size_t)(wk*32 + nt)*32 + ln);
            mma_bf16(d[half][0], A0[wk], u.x, u.y);   // chain depth 4
            mma_bf16(d[half][1], A0[wk], u.z, u.w);   // chain depth 8
            mma_bf16(d[half][1], A1[wk], u.x, u.y);
        }
        const int c0 = nt*8 + q*2;
        cc_[half][0] = *(const float2*)(cst + (size_t)gr*256 + c0);
        cc_[half][1] = *(const float2*)(cst + (size_t)(gr+8)*256 + c0);
    }
}

__device__ __forceinline__ void wide_epi(const float d[2][2][4], const float2 cc_[2][2],
                                         uint32_t ah[4], uint32_t al[4])
{
    #pragma unroll
    for (int half = 0; half < 2; ++half) {
        float h0 = ftanh(d[half][0][0] + d[half][1][0] + cc_[half][0].x);
        float h1 = ftanh(d[half][0][1] + d[half][1][1] + cc_[half][0].y);
        float h2 = ftanh(d[half][0][2] + d[half][1][2] + cc_[half][1].x);
        float h3 = ftanh(d[half][0][3] + d[half][1][3] + cc_[half][1].y);
        split2(h0, h1, ah[half*2],   al[half*2]);
        split2(h2, h3, ah[half*2+1], al[half*2+1]);
    }
}

__device__ __forceinline__ void narrow_step(const uint32_t ah[4], const uint32_t al[4],
                                            const uint4* __restrict__ Wn, int kt, int ln,
                                            float nacc[8][4])
{
    #pragma unroll
    for (int nt = 0; nt < 8; ++nt) {
        uint4 u = __ldg(Wn + (size_t)(kt*8 + nt)*32 + ln);
        mma_bf16(nacc[nt], ah, u.x, u.y);
        mma_bf16(nacc[nt], ah, u.z, u.w);
        mma_bf16(nacc[nt], al, u.x, u.y);
    }
}

__device__ __forceinline__ void fused_wide_narrow(
    const uint32_t Ah[4][4], const uint32_t Al[4][4],
    const uint4* __restrict__ Wwide, const uint4* __restrict__ Wnarrow,
    const float* __restrict__ cst, int ln, float nacc[8][4])
{
    const int gr = ln >> 2, q = ln & 3;
    #pragma unroll
    for (int nt = 0; nt < 8; nt++)
        #pragma unroll
        for (int i = 0; i < 4; i++) nacc[nt][i] = 0.f;

    float d[2][2][4]; float2 cc_[2][2];
    uint32_t ah[4], al[4];
    wide_mma(Ah, Al, Wwide, cst, 0, ln, gr, q, d, cc_);
    wide_epi(d, cc_, ah, al);
    #pragma unroll 1
    for (int kt = 1; kt < 16; ++kt) {
        float d2[2][2][4]; float2 cc2[2][2];
        wide_mma(Ah, Al, Wwide, cst, kt, ln, gr, q, d2, cc2);  // fills pipe
        narrow_step(ah, al, Wnarrow, kt-1, ln, nacc);          // overlaps wide latency
        wide_epi(d2, cc2, ah, al);
    }
    narrow_step(ah, al, Wnarrow, 15, ln, nacc);
}

// ================= fused step: gather -> (wide+narrow)x2, register-chained =================
#define A_STRIDE   144
#define AH_OFF     0
#define AL_OFF     2304
#define WARP_BYTES 4608
#define STEP_SMEM  (4*WARP_BYTES)

__global__ __launch_bounds__(128, 4)
void k_step(int t, const float* __restrict__ cc, const int* __restrict__ conn,
            const float* __restrict__ nid, const float* __restrict__ sb2,
            const float* __restrict__ mb2, float* __restrict__ out)
{
    extern __shared__ char smem[];
    const int tid = threadIdx.x;
    const int w   = tid >> 5, ln = tid & 31;
    char*    wmem = smem + w*WARP_BYTES;
    const uint32_t wsm = smem_u32(smem) + w*WARP_BYTES;

    const int b      = blockIdx.y;
    const int ntblk  = blockIdx.x;
    const int n0     = ntblk*64;
    const int nfirst = n0 + w*16;
    const int sel    = t & 1;
    const size_t growbase = (size_t)b*NN + nfirst;

    // ---- phase 0: gather (+inject) -> bf16 h/l A-tile in smem ----
    {
        const u64*    mq  = (const u64*)g_msg2[sel] + (size_t)b*NN*32;
        const int4*   cn4 = (const int4*)conn;
        const float4* ws4 = (const float4*)g_wsig4;
        #pragma unroll 1
        for (int g = 0; g < 16; ++g) {
            const int n = nfirst + g;
            const size_t cb = (size_t)n*8;
            const size_t wb = ((size_t)b*NN + n)*8;
            u64 a0 = 0ull, a1 = 0ull;
            #pragma unroll
            for (int kq = 0; kq < 8; ++kq) {
                int4   id = __ldg(cn4 + cb + kq);
                float4 wt = __ldg(ws4 + wb + kq);
                ffma2(a0, pack2(wt.x), mq[(size_t)id.x*32 + ln]);
                ffma2(a1, pack2(wt.y), mq[(size_t)id.y*32 + ln]);
                ffma2(a0, pack2(wt.z), mq[(size_t)id.z*32 + ln]);
                ffma2(a1, pack2(wt.w), mq[(size_t)id.w*32 + ln]);
            }
            float2 v0 = unpack2(a0), v1 = unpack2(a1);
            float x0 = v0.x + v1.x, x1 = v0.y + v1.y;
            if ((n & 127) < 4) {
                float2 cv = *(const float2*)(cc + ((size_t)b*TT + t)*2048 + (n>>7)*64 + ln*2);
                x0 += cv.x; x1 += cv.y;
            }
            uint32_t hi, lo;
            split2(x0, x1, hi, lo);
            *(uint32_t*)(wmem + AH_OFF + g*A_STRIDE + ln*4) = hi;
            *(uint32_t*)(wmem + AL_OFF + g*A_STRIDE + ln*4) = lo;
        }
    }
    __syncwarp();

    // load gather A-frags once; smem A region free afterwards.
    // These SAME registers are reused for the phase-3 A-fragments (h), keeping
    // the live register set under the 128-reg cap for 4 CTAs/SM.
    uint32_t Ah[4][4], Al[4][4];
    {
        const int row = ln & 15;
        const uint32_t coff = (uint32_t)((ln >> 4) << 4);
        #pragma unroll
        for (int kt = 0; kt < 4; kt++) {
            uint32_t ad = wsm + AH_OFF + row*A_STRIDE + kt*32 + coff;
            ldm_x4(Ah[kt], ad);
            ldm_x4(Al[kt], ad + (AL_OFF - AH_OFF));
        }
    }
    __syncwarp();

    const int gr = ln >> 2, q = ln & 3;
    float nacc[8][4];

    // ---- phases 1+2: hid = tanh(recv@Wsi + sconst); nacc = hid@Ws2 ----
    fused_wide_narrow(Ah, Al, g_Wpk, g_Wpk + 4096,
                      g_sconst + growbase*256, ln, nacc);

    // ---- phase 2 epilogue: h update; OVERWRITE Ah/Al with phase-3 A-frags ----
    {
        const float dv0 = g_d[growbase + gr];
        const float dv1 = g_d[growbase + gr + 8];
        float2 ho0[8], ho1[8];
        #pragma unroll
        for (int nt = 0; nt < 8; ++nt) {
            const int ci = (nt*8 + q*2) >> 1;
            ho0[nt] = g_h2[(growbase + gr)*32 + ci];
            ho1[nt] = g_h2[(growbase + gr + 8)*32 + ci];
        }
        #pragma unroll
        for (int nt = 0; nt < 8; ++nt) {
            const int c0 = nt*8 + q*2;
            float2 bb = *(const float2*)(sb2 + c0);
            // row gr
            {
                float u0 = ftanh(nacc[nt][0] + bb.x), u1 = ftanh(nacc[nt][1] + bb.y);
                float hv0 = dv0*ho0[nt].x + (1.f-dv0)*u0, hv1 = dv0*ho0[nt].y + (1.f-dv0)*u1;
                g_h2[(growbase + gr)*32 + (c0 >> 1)] = make_float2(hv0, hv1);
                split2(hv0, hv1, Ah[nt>>1][(nt&1)*2], Al[nt>>1][(nt&1)*2]);
            }
            // row gr+8
            {
                float u0 = ftanh(nacc[nt][2] + bb.x), u1 = ftanh(nacc[nt][3] + bb.y);
                float hv0 = dv1*ho1[nt].x + (1.f-dv1)*u0, hv1 = dv1*ho1[nt].y + (1.f-dv1)*u1;
                g_h2[(growbase + gr + 8)*32 + (c0 >> 1)] = make_float2(hv0, hv1);
                split2(hv0, hv1, Ah[nt>>1][(nt&1)*2+1], Al[nt>>1][(nt&1)*2+1]);
            }
        }
    }

    // ---- phases 3+4: mh = tanh(h@Wmh + mconst); nacc = mh@Wm2 ----
    fused_wide_narrow(Ah, Al, g_Wpk + 2*4096, g_Wpk + 3*4096,
                      g_mconst + growbase*256, ln, nacc);

    // ---- phase 4 epilogue: msg = tanh(.+mb2)+nid; readout ----
    {
        const int roflag = (ntblk & 1) && (w == 3);
        float2* msgout = g_msg2[sel ^ 1];
        float* s_ro = (float*)wmem;      // gather A region, free now
        #pragma unroll
        for (int nt = 0; nt < 8; ++nt) {
            const int c0 = nt*8 + q*2;
            float2 bb = *(const float2*)(mb2 + c0);
            // row gr
            {
                int n = nfirst + gr;
                size_t grow = growbase + gr;
                float2 nv = *(const float2*)(nid + (size_t)n*64 + c0);
                float m0 = ftanh(nacc[nt][0] + bb.x) + nv.x;
                float m1 = ftanh(nacc[nt][1] + bb.y) + nv.y;
                msgout[grow*32 + (c0 >> 1)] = make_float2(m0, m1);
            }
            // row gr+8
            {
                int n = nfirst + gr + 8;
                size_t grow = growbase + gr + 8;
                float2 nv = *(const float2*)(nid + (size_t)n*64 + c0);
                float m0 = ftanh(nacc[nt][2] + bb.x) + nv.x;
                float m1 = ftanh(nacc[nt][3] + bb.y) + nv.y;
                msgout[grow*32 + (c0 >> 1)] = make_float2(m0, m1);
                if (roflag && gr >= 4)
                    *(float2*)(s_ro + (gr-4)*64 + c0) = make_float2(m0, m1);
            }
        }
        __syncwarp();
        if (roflag) {
            size_t obase = ((size_t)b*TT + t)*2048 + (ntblk >> 1)*64;
            float v0 = 0.25f*(s_ro[ln]      + s_ro[64+ln]  + s_ro[128+ln] + s_ro[192+ln]);
            float v1 = 0.25f*(s_ro[32+ln]   + s_ro[96+ln]  + s_ro[160+ln] + s_ro[224+ln]);
            out[obase + ln]      = v0;
            out[obase + 32 + ln] = v1;
        }
    }
}

// ================= launcher =================
extern "C" void kernel_launch(void* const* d_in, const int* in_sizes, int n_in,
                              void* d_out, int out_size)
{
    const float* cc      = (const float*)d_in[0];
    const float* h_in    = (const float*)d_in[1];
    const float* msg_in  = (const float*)d_in[2];
    const float* wconn   = (const float*)d_in[3];
    const float* declog  = (const float*)d_in[4];
    const float* prim_in = (const float*)d_in[5];
    const float* heb     = (const float*)d_in[6];
    const float* sw1     = (const float*)d_in[7];
    const float* sb1     = (const float*)d_in[8];
    const float* sw2     = (const float*)d_in[9];
    const float* sb2     = (const float*)d_in[10];
    const float* mw1     = (const float*)d_in[11];
    const float* mb1     = (const float*)d_in[12];
    const float* mw2     = (const float*)d_in[13];
    const float* mb2     = (const float*)d_in[14];
    const float* modw1   = (const float*)d_in[15];
    const float* modb1   = (const float*)d_in[16];
    const float* modw2   = (const float*)d_in[17];
    const float* modb2   = (const float*)d_in[18];
    const float* nid     = (const float*)d_in[19];
    const int*   conn    = (const int*)d_in[20];
    float* out = (float*)d_out;

    cudaFuncSetAttribute(k_step, cudaFuncAttributeMaxDynamicSharedMemorySize, STEP_SMEM);

    k_init<<<256, 256>>>(h_in, msg_in, sw1, sw2, mw1, mw2);
    k_mod<<<NN, 256>>>(h_in, heb, declog, prim_in, wconn,
                       modw1, modb1, modw2, modb2, nid);
    k_const<<<dim3(512, 2), 256>>>(sb1, mb1, nid);

    for (int t = 0; t < TT; ++t) {
        k_step<<<dim3(NN/64, BSZ), 128, STEP_SMEM>>>(t, cc, conn, nid, sb2, mb2, out);
    }
}